// round 12
// baseline (speedup 1.0000x reference)
#include <cuda_runtime.h>
#include <cuda_fp16.h>
#include <math.h>
#include <stdint.h>

#define D_MODEL 1024
#define SEQ 2048
#define BATCH 2
#define NHEAD 16
#define HD 64
#define ROWS (BATCH*SEQ)   // 4096

// ---------------- scratch ----------------
__device__ float  g_XN [ROWS * D_MODEL];
__device__ __half g_XNh[ROWS * D_MODEL];
__device__ __half g_QKVh[ROWS * 3 * D_MODEL];
__device__ __half g_Oh [ROWS * D_MODEL];
__device__ float  g_H  [ROWS * D_MODEL];
__device__ float  g_HN [ROWS * D_MODEL];
__device__ __half g_HNh[ROWS * D_MODEL];
__device__ __half g_Gh [ROWS * 4 * D_MODEL];
__device__ __half g_Wqkv [3 * D_MODEL * D_MODEL];
__device__ __half g_Wproj[D_MODEL * D_MODEL];
__device__ __half g_Wfc  [4 * D_MODEL * D_MODEL];
__device__ __half g_Wpr2 [D_MODEL * 4 * D_MODEL];

// ---------------- weight -> fp16 transpose ----------------
__global__ __launch_bounds__(256) void cvt_t_kernel(const float* __restrict__ W,
                                                    __half* __restrict__ Wt,
                                                    int K, int N)
{
    __shared__ float tile[32][33];
    int n0 = blockIdx.x * 32, k0 = blockIdx.y * 32;
    int tx = threadIdx.x & 31, ty = threadIdx.x >> 5;
    #pragma unroll
    for (int j = 0; j < 4; j++) {
        int k = k0 + ty + j * 8;
        tile[ty + j * 8][tx] = W[(size_t)k * N + n0 + tx];
    }
    __syncthreads();
    #pragma unroll
    for (int j = 0; j < 4; j++) {
        int n = n0 + ty + j * 8;
        Wt[(size_t)n * K + k0 + tx] = __float2half(tile[tx][ty + j * 8]);
    }
}

// ---------------- LayerNorm ----------------
__global__ __launch_bounds__(256) void ln_kernel(const float* __restrict__ x,
                                                 const float* __restrict__ w,
                                                 const float* __restrict__ b,
                                                 float* __restrict__ y,
                                                 __half* __restrict__ yh)
{
    int row = blockIdx.x;
    int t = threadIdx.x;
    const float4* xr = (const float4*)(x + (size_t)row * D_MODEL);
    float4 v = xr[t];
    float s  = v.x + v.y + v.z + v.w;
    float sq = v.x*v.x + v.y*v.y + v.z*v.z + v.w*v.w;
    #pragma unroll
    for (int o = 16; o > 0; o >>= 1) {
        s  += __shfl_xor_sync(0xFFFFFFFFu, s, o);
        sq += __shfl_xor_sync(0xFFFFFFFFu, sq, o);
    }
    __shared__ float ss[8], ssq[8];
    int wid = t >> 5, lane = t & 31;
    if (lane == 0) { ss[wid] = s; ssq[wid] = sq; }
    __syncthreads();
    if (wid == 0) {
        s  = (lane < 8) ? ss[lane]  : 0.0f;
        sq = (lane < 8) ? ssq[lane] : 0.0f;
        #pragma unroll
        for (int o = 4; o > 0; o >>= 1) {
            s  += __shfl_xor_sync(0xFFFFFFFFu, s, o);
            sq += __shfl_xor_sync(0xFFFFFFFFu, sq, o);
        }
        if (lane == 0) {
            float mu = s * (1.0f / D_MODEL);
            ss[0]  = mu;
            ssq[0] = rsqrtf(sq * (1.0f / D_MODEL) - mu * mu + 1e-5f);
        }
    }
    __syncthreads();
    float mu = ss[0], rstd = ssq[0];
    float4 wv = ((const float4*)w)[t];
    float4 bv = ((const float4*)b)[t];
    float4 r;
    r.x = (v.x - mu) * rstd * wv.x + bv.x;
    r.y = (v.y - mu) * rstd * wv.y + bv.y;
    r.z = (v.z - mu) * rstd * wv.z + bv.z;
    r.w = (v.w - mu) * rstd * wv.w + bv.w;
    ((float4*)(y + (size_t)row * D_MODEL))[t] = r;
    __half2 h0 = __floats2half2_rn(r.x, r.y);
    __half2 h1 = __floats2half2_rn(r.z, r.w);
    uint2 u = { *(uint32_t*)&h0, *(uint32_t*)&h1 };
    *(uint2*)(yh + (size_t)row * D_MODEL + t * 4) = u;
}

// ---------------- MMA helpers ----------------
__device__ __forceinline__ void mma_f16(float* d, const uint32_t* a, const uint32_t* b) {
    asm volatile(
        "mma.sync.aligned.m16n8k16.row.col.f32.f16.f16.f32 "
        "{%0,%1,%2,%3}, {%4,%5,%6,%7}, {%8,%9}, {%0,%1,%2,%3};\n"
        : "+f"(d[0]), "+f"(d[1]), "+f"(d[2]), "+f"(d[3])
        : "r"(a[0]), "r"(a[1]), "r"(a[2]), "r"(a[3]), "r"(b[0]), "r"(b[1]));
}
__device__ __forceinline__ void ldsm_x4(uint32_t& r0, uint32_t& r1, uint32_t& r2, uint32_t& r3,
                                        uint32_t addr) {
    asm volatile("ldmatrix.sync.aligned.m8n8.x4.shared.b16 {%0,%1,%2,%3}, [%4];"
                 : "=r"(r0), "=r"(r1), "=r"(r2), "=r"(r3) : "r"(addr));
}
__device__ __forceinline__ void ldsm_x4_t(uint32_t& r0, uint32_t& r1, uint32_t& r2, uint32_t& r3,
                                          uint32_t addr) {
    asm volatile("ldmatrix.sync.aligned.m8n8.x4.trans.shared.b16 {%0,%1,%2,%3}, [%4];"
                 : "=r"(r0), "=r"(r1), "=r"(r2), "=r"(r3) : "r"(addr));
}
__device__ __forceinline__ void cp16(uint32_t dst, const void* src) {
    asm volatile("cp.async.cg.shared.global [%0], [%1], 16;\n" :: "r"(dst), "l"(src));
}
__device__ __forceinline__ void cp_commit() {
    asm volatile("cp.async.commit_group;\n");
}
template <int N>
__device__ __forceinline__ void cp_wait() {
    asm volatile("cp.async.wait_group %0;\n" :: "n"(N));
}

// ---------------- fp16 GEMM: 128 thr, warp tile 64x64, BK=64, 3-stage ----------------
#define EPI_BIAS      0
#define EPI_BIAS_GELU 1
#define EPI_BIAS_RES  2
#define EPI_BIAS_QKV  3

#define ROW_BYTES 144
#define STAGE_BYTES (128 * ROW_BYTES)
#define GEMM_STAGES 3
#define GEMM_SMEM_BYTES (GEMM_STAGES * 2 * STAGE_BYTES)   // 110592

template <int EPI>
__global__ __launch_bounds__(128, 2) void mma_gemm(const __half* __restrict__ A,
                                                   const __half* __restrict__ Bt,
                                                   const float* __restrict__ bias,
                                                   const float* __restrict__ res,
                                                   void* __restrict__ Cv,
                                                   int M, int N, int K)
{
    extern __shared__ uint8_t smem8[];
    uint32_t sbA = (uint32_t)__cvta_generic_to_shared(smem8);
    uint32_t sbB = sbA + GEMM_STAGES * STAGE_BYTES;

    int tid = threadIdx.x;
    int wid = tid >> 5, lane = tid & 31;
    int gid = lane >> 2, tig = lane & 3;
    int warp_m = wid & 1, warp_n = wid >> 1;   // 2x2 warp grid, 64x64 per warp
    int bx = blockIdx.x, by = blockIdx.y;

    // cp.async coords: 8 x 16B per matrix per stage per thread (128 threads)
    const __half* Asrc[8];
    const __half* Bsrc[8];
    uint32_t Adst[8], Bdst[8];
    #pragma unroll
    for (int j = 0; j < 8; j++) {
        int q = tid + j * 128;
        int r = q >> 3, c = q & 7;
        Asrc[j] = A  + (size_t)(by * 128 + r) * K + c * 8;
        Bsrc[j] = Bt + (size_t)(bx * 128 + r) * K + c * 8;
        Adst[j] = sbA + r * ROW_BYTES + c * 16;
        Bdst[j] = sbB + r * ROW_BYTES + c * 16;
    }

    uint32_t a_lm = sbA + (warp_m * 64 + (lane & 15)) * ROW_BYTES + ((lane >> 4) * 16);
    uint32_t b_lm = sbB + (warp_n * 64 + (lane & 15)) * ROW_BYTES + ((lane >> 4) * 16);

    float acc[4][8][4];
    #pragma unroll
    for (int mt = 0; mt < 4; mt++)
        #pragma unroll
        for (int nt = 0; nt < 8; nt++)
            #pragma unroll
            for (int r = 0; r < 4; r++) acc[mt][nt][r] = 0.0f;

    int nIter = K >> 6;
    #pragma unroll
    for (int s = 0; s < 2; s++) {
        #pragma unroll
        for (int j = 0; j < 8; j++) {
            cp16(Adst[j] + s * STAGE_BYTES, Asrc[j] + s * 64);
            cp16(Bdst[j] + s * STAGE_BYTES, Bsrc[j] + s * 64);
        }
        cp_commit();
    }

    for (int it = 0; it < nIter; it++) {
        cp_wait<1>();
        __syncthreads();
        if (it + 2 < nIter) {
            int sb = (it + 2) % GEMM_STAGES;
            int k0 = (it + 2) << 6;
            #pragma unroll
            for (int j = 0; j < 8; j++) {
                cp16(Adst[j] + sb * STAGE_BYTES, Asrc[j] + k0);
                cp16(Bdst[j] + sb * STAGE_BYTES, Bsrc[j] + k0);
            }
        }
        cp_commit();

        int buf = it % GEMM_STAGES;
        uint32_t abase = a_lm + buf * STAGE_BYTES;
        uint32_t bbase = b_lm + buf * STAGE_BYTES;
        #pragma unroll
        for (int ks = 0; ks < 4; ks++) {
            uint32_t af[4][4], bf[8][2];
            #pragma unroll
            for (int mt = 0; mt < 4; mt++)
                ldsm_x4(af[mt][0], af[mt][1], af[mt][2], af[mt][3],
                        abase + mt * 16 * ROW_BYTES + ks * 32);
            #pragma unroll
            for (int p = 0; p < 4; p++)
                ldsm_x4(bf[2*p][0], bf[2*p+1][0], bf[2*p][1], bf[2*p+1][1],
                        bbase + p * 16 * ROW_BYTES + ks * 32);
            #pragma unroll
            for (int mt = 0; mt < 4; mt++)
                #pragma unroll
                for (int nt = 0; nt < 8; nt++)
                    mma_f16(acc[mt][nt], af[mt], bf[nt]);
        }
    }

    // epilogue
    #pragma unroll
    for (int mt = 0; mt < 4; mt++) {
        #pragma unroll
        for (int nt = 0; nt < 8; nt++) {
            int row0 = by * 128 + warp_m * 64 + mt * 16 + gid;
            int col  = bx * 128 + warp_n * 64 + nt * 8 + tig * 2;
            float b0 = bias[col], b1 = bias[col + 1];
            #pragma unroll
            for (int half_i = 0; half_i < 2; half_i++) {
                int row = row0 + half_i * 8;
                float v0 = acc[mt][nt][half_i * 2 + 0] + b0;
                float v1 = acc[mt][nt][half_i * 2 + 1] + b1;
                if (EPI == EPI_BIAS_QKV) {
                    if (col < D_MODEL) { v0 *= 0.125f; v1 *= 0.125f; }
                    __half2 hv = __floats2half2_rn(v0, v1);
                    *(__half2*)((__half*)Cv + (size_t)row * N + col) = hv;
                } else if (EPI == EPI_BIAS_GELU) {
                    v0 = 0.5f * v0 * (1.0f + erff(v0 * 0.70710678118654752f));
                    v1 = 0.5f * v1 * (1.0f + erff(v1 * 0.70710678118654752f));
                    __half2 hv = __floats2half2_rn(v0, v1);
                    *(__half2*)((__half*)Cv + (size_t)row * N + col) = hv;
                } else {
                    if (EPI == EPI_BIAS_RES) {
                        float2 rv = *(const float2*)(res + (size_t)row * N + col);
                        v0 += rv.x; v1 += rv.y;
                    }
                    float2 o2 = { v0, v1 };
                    *(float2*)((float*)Cv + (size_t)row * N + col) = o2;
                }
            }
        }
    }
}

// ---------------- Flash attention: fp16 MMA + ldmatrix ----------------
#define AROW 144
#define ATTN_SMEM (3 * 64 * AROW)

__global__ __launch_bounds__(128) void attn_kernel(const __half* __restrict__ qkv,
                                                   __half* __restrict__ out)
{
    extern __shared__ uint8_t smem8[];
    uint32_t sb = (uint32_t)__cvta_generic_to_shared(smem8);
    uint8_t* QP = smem8;
    uint8_t* Ks = smem8 + 64 * AROW;
    uint8_t* Vs = smem8 + 2 * 64 * AROW;
    uint32_t sbQP = sb, sbK = sb + 64 * AROW, sbV = sb + 2 * 64 * AROW;

    int bh = blockIdx.y;
    int b = bh >> 4, h = bh & 15;
    int q0 = blockIdx.x * 64;
    int tid = threadIdx.x;
    int wid = tid >> 5, lane = tid & 31;
    int gid = lane >> 2, tig = lane & 3;
    int m0 = wid * 16;

    for (int i = tid; i < 64 * 8; i += 128) {
        int r = i >> 3, c8 = (i & 7) * 8;
        uint4 u = *(const uint4*)(qkv + (size_t)(b * SEQ + q0 + r) * 3 * D_MODEL + h * HD + c8);
        *(uint4*)(QP + r * AROW + c8 * 2) = u;
    }
    __syncthreads();

    uint32_t q_lm = sbQP + (m0 + (lane & 15)) * AROW + ((lane >> 4) * 16);
    uint32_t qa[4][4];
    #pragma unroll
    for (int ks = 0; ks < 4; ks++)
        ldsm_x4(qa[ks][0], qa[ks][1], qa[ks][2], qa[ks][3], q_lm + ks * 32);
    __syncthreads();

    uint32_t k_lm = sbK + ((lane & 15)) * AROW + ((lane >> 4) * 16);
    uint32_t p_lm = q_lm;

    float o[8][4];
    #pragma unroll
    for (int nt = 0; nt < 8; nt++)
        #pragma unroll
        for (int j = 0; j < 4; j++) o[nt][j] = 0.0f;
    float ms0 = -3.0e38f, ms1 = -3.0e38f, ls0 = 0.0f, ls1 = 0.0f;

    for (int kt = 0; kt <= q0; kt += 64) {
        for (int i = tid; i < 64 * 8; i += 128) {
            int r = i >> 3, c8 = (i & 7) * 8;
            const __half* base = qkv + (size_t)(b * SEQ + kt + r) * 3 * D_MODEL + h * HD + c8;
            *(uint4*)(Ks + r * AROW + c8 * 2) = *(const uint4*)(base + D_MODEL);
            *(uint4*)(Vs + r * AROW + c8 * 2) = *(const uint4*)(base + 2 * D_MODEL);
        }
        __syncthreads();

        float sc[8][4];
        #pragma unroll
        for (int nt = 0; nt < 8; nt++)
            #pragma unroll
            for (int j = 0; j < 4; j++) sc[nt][j] = 0.0f;
        #pragma unroll
        for (int ks = 0; ks < 4; ks++) {
            uint32_t bf[8][2];
            #pragma unroll
            for (int p = 0; p < 4; p++)
                ldsm_x4(bf[2*p][0], bf[2*p+1][0], bf[2*p][1], bf[2*p+1][1],
                        k_lm + p * 16 * AROW + ks * 32);
            #pragma unroll
            for (int nt = 0; nt < 8; nt++)
                mma_f16(sc[nt], qa[ks], bf[nt]);
        }

        if (kt == q0) {
            int r0 = m0 + gid, r1 = r0 + 8;
            #pragma unroll
            for (int nt = 0; nt < 8; nt++) {
                int c0 = nt * 8 + tig * 2;
                if (c0     > r0) sc[nt][0] = -3.0e38f;
                if (c0 + 1 > r0) sc[nt][1] = -3.0e38f;
                if (c0     > r1) sc[nt][2] = -3.0e38f;
                if (c0 + 1 > r1) sc[nt][3] = -3.0e38f;
            }
        }

        float tm0 = -3.0e38f, tm1 = -3.0e38f;
        #pragma unroll
        for (int nt = 0; nt < 8; nt++) {
            tm0 = fmaxf(tm0, fmaxf(sc[nt][0], sc[nt][1]));
            tm1 = fmaxf(tm1, fmaxf(sc[nt][2], sc[nt][3]));
        }
        #pragma unroll
        for (int off = 1; off <= 2; off <<= 1) {
            tm0 = fmaxf(tm0, __shfl_xor_sync(0xFFFFFFFFu, tm0, off));
            tm1 = fmaxf(tm1, __shfl_xor_sync(0xFFFFFFFFu, tm1, off));
        }
        float mn0 = fmaxf(ms0, tm0), mn1 = fmaxf(ms1, tm1);
        float cc0 = __expf(ms0 - mn0), cc1 = __expf(ms1 - mn1);
        ms0 = mn0; ms1 = mn1;
        float ps0 = 0.0f, ps1 = 0.0f;
        #pragma unroll
        for (int nt = 0; nt < 8; nt++) {
            sc[nt][0] = __expf(sc[nt][0] - mn0); ps0 += sc[nt][0];
            sc[nt][1] = __expf(sc[nt][1] - mn0); ps0 += sc[nt][1];
            sc[nt][2] = __expf(sc[nt][2] - mn1); ps1 += sc[nt][2];
            sc[nt][3] = __expf(sc[nt][3] - mn1); ps1 += sc[nt][3];
        }
        #pragma unroll
        for (int off = 1; off <= 2; off <<= 1) {
            ps0 += __shfl_xor_sync(0xFFFFFFFFu, ps0, off);
            ps1 += __shfl_xor_sync(0xFFFFFFFFu, ps1, off);
        }
        ls0 = ls0 * cc0 + ps0;
        ls1 = ls1 * cc1 + ps1;
        #pragma unroll
        for (int nt = 0; nt < 8; nt++) {
            o[nt][0] *= cc0; o[nt][1] *= cc0;
            o[nt][2] *= cc1; o[nt][3] *= cc1;
        }

        __syncwarp();
        #pragma unroll
        for (int nt = 0; nt < 8; nt++) {
            int c0 = nt * 8 + tig * 2;
            __half2 p0 = __floats2half2_rn(sc[nt][0], sc[nt][1]);
            __half2 p1 = __floats2half2_rn(sc[nt][2], sc[nt][3]);
            *(__half2*)(QP + (m0 + gid    ) * AROW + c0 * 2) = p0;
            *(__half2*)(QP + (m0 + gid + 8) * AROW + c0 * 2) = p1;
        }
        __syncwarp();

        #pragma unroll
        for (int ks = 0; ks < 4; ks++) {
            uint32_t pf[4];
            ldsm_x4(pf[0], pf[1], pf[2], pf[3], p_lm + ks * 32);
            uint32_t v_base = sbV + (ks * 16 + (lane & 15)) * AROW + ((lane >> 4) * 16);
            #pragma unroll
            for (int p = 0; p < 4; p++) {
                uint32_t bf[2][2];
                ldsm_x4_t(bf[0][0], bf[0][1], bf[1][0], bf[1][1], v_base + p * 32);
                mma_f16(o[2*p    ], pf, bf[0]);
                mma_f16(o[2*p + 1], pf, bf[1]);
            }
        }
        __syncthreads();
    }

    float inv0 = 1.0f / ls0, inv1 = 1.0f / ls1;
    int row0 = b * SEQ + q0 + m0 + gid;
    int row1 = row0 + 8;
    #pragma unroll
    for (int nt = 0; nt < 8; nt++) {
        int col = h * HD + nt * 8 + tig * 2;
        *(__half2*)(out + (size_t)row0 * D_MODEL + col) = __floats2half2_rn(o[nt][0] * inv0, o[nt][1] * inv0);
        *(__half2*)(out + (size_t)row1 * D_MODEL + col) = __floats2half2_rn(o[nt][2] * inv1, o[nt][3] * inv1);
    }
}

// ---------------- launch ----------------
extern "C" void kernel_launch(void* const* d_in, const int* in_sizes, int n_in,
                              void* d_out, int out_size)
{
    const float* x          = (const float*)d_in[0];
    const float* ln1_w      = (const float*)d_in[1];
    const float* ln1_b      = (const float*)d_in[2];
    const float* qkv_w      = (const float*)d_in[3];
    const float* qkv_b      = (const float*)d_in[4];
    const float* attn_out_w = (const float*)d_in[5];
    const float* attn_out_b = (const float*)d_in[6];
    const float* ln2_w      = (const float*)d_in[7];
    const float* ln2_b      = (const float*)d_in[8];
    const float* c_fc_w     = (const float*)d_in[9];
    const float* c_fc_b     = (const float*)d_in[10];
    const float* c_proj_w   = (const float*)d_in[11];
    const float* c_proj_b   = (const float*)d_in[12];
    float* out = (float*)d_out;

    float *XN, *H, *HN;
    __half *XNh, *QKVh, *Oh, *HNh, *Gh, *Wqkv, *Wproj, *Wfc, *Wpr2;
    cudaGetSymbolAddress((void**)&XN,   g_XN);
    cudaGetSymbolAddress((void**)&XNh,  g_XNh);
    cudaGetSymbolAddress((void**)&QKVh, g_QKVh);
    cudaGetSymbolAddress((void**)&Oh,   g_Oh);
    cudaGetSymbolAddress((void**)&H,    g_H);
    cudaGetSymbolAddress((void**)&HN,   g_HN);
    cudaGetSymbolAddress((void**)&HNh,  g_HNh);
    cudaGetSymbolAddress((void**)&Gh,   g_Gh);
    cudaGetSymbolAddress((void**)&Wqkv, g_Wqkv);
    cudaGetSymbolAddress((void**)&Wproj,g_Wproj);
    cudaGetSymbolAddress((void**)&Wfc,  g_Wfc);
    cudaGetSymbolAddress((void**)&Wpr2, g_Wpr2);

    cudaFuncSetAttribute(mma_gemm<EPI_BIAS_QKV>,  cudaFuncAttributeMaxDynamicSharedMemorySize, GEMM_SMEM_BYTES);
    cudaFuncSetAttribute(mma_gemm<EPI_BIAS_GELU>, cudaFuncAttributeMaxDynamicSharedMemorySize, GEMM_SMEM_BYTES);
    cudaFuncSetAttribute(mma_gemm<EPI_BIAS_RES>,  cudaFuncAttributeMaxDynamicSharedMemorySize, GEMM_SMEM_BYTES);
    cudaFuncSetAttribute(attn_kernel,             cudaFuncAttributeMaxDynamicSharedMemorySize, ATTN_SMEM);

    cvt_t_kernel<<<dim3(3 * D_MODEL / 32, D_MODEL / 32), 256>>>(qkv_w, Wqkv, D_MODEL, 3 * D_MODEL);
    cvt_t_kernel<<<dim3(D_MODEL / 32, D_MODEL / 32), 256>>>(attn_out_w, Wproj, D_MODEL, D_MODEL);
    cvt_t_kernel<<<dim3(4 * D_MODEL / 32, D_MODEL / 32), 256>>>(c_fc_w, Wfc, D_MODEL, 4 * D_MODEL);
    cvt_t_kernel<<<dim3(D_MODEL / 32, 4 * D_MODEL / 32), 256>>>(c_proj_w, Wpr2, 4 * D_MODEL, D_MODEL);

    ln_kernel<<<ROWS, 256>>>(x, ln1_w, ln1_b, XN, XNh);

    mma_gemm<EPI_BIAS_QKV><<<dim3(3 * D_MODEL / 128, ROWS / 128), 128, GEMM_SMEM_BYTES>>>(
        XNh, Wqkv, qkv_b, nullptr, QKVh, ROWS, 3 * D_MODEL, D_MODEL);

    attn_kernel<<<dim3(SEQ / 64, BATCH * NHEAD), 128, ATTN_SMEM>>>(QKVh, Oh);

    mma_gemm<EPI_BIAS_RES><<<dim3(D_MODEL / 128, ROWS / 128), 128, GEMM_SMEM_BYTES>>>(
        Oh, Wproj, attn_out_b, XN, H, ROWS, D_MODEL, D_MODEL);

    ln_kernel<<<ROWS, 256>>>(H, ln2_w, ln2_b, HN, HNh);

    mma_gemm<EPI_BIAS_GELU><<<dim3(4 * D_MODEL / 128, ROWS / 128), 128, GEMM_SMEM_BYTES>>>(
        HNh, Wfc, c_fc_b, nullptr, Gh, ROWS, 4 * D_MODEL, D_MODEL);

    mma_gemm<EPI_BIAS_RES><<<dim3(D_MODEL / 128, ROWS / 128), 128, GEMM_SMEM_BYTES>>>(
        Gh, Wpr2, c_proj_b, HN, out, ROWS, D_MODEL, 4 * D_MODEL);
}

// round 13
// speedup vs baseline: 1.0330x; 1.0330x over previous
#include <cuda_runtime.h>
#include <cuda_fp16.h>
#include <math.h>
#include <stdint.h>

#define D_MODEL 1024
#define SEQ 2048
#define BATCH 2
#define NHEAD 16
#define HD 64
#define ROWS (BATCH*SEQ)   // 4096

// ---------------- scratch ----------------
__device__ float  g_XN [ROWS * D_MODEL];
__device__ __half g_XNh[ROWS * D_MODEL];
__device__ float  g_QKV[ROWS * 3 * D_MODEL];
__device__ __half g_Oh [ROWS * D_MODEL];
__device__ float  g_H  [ROWS * D_MODEL];
__device__ float  g_HN [ROWS * D_MODEL];
__device__ __half g_HNh[ROWS * D_MODEL];
__device__ __half g_Gh [ROWS * 4 * D_MODEL];
__device__ __half g_Wqkv [3 * D_MODEL * D_MODEL];
__device__ __half g_Wproj[D_MODEL * D_MODEL];
__device__ __half g_Wfc  [4 * D_MODEL * D_MODEL];
__device__ __half g_Wpr2 [D_MODEL * 4 * D_MODEL];

// ---------------- fused weight transpose: all 4 weights in ONE launch ----------------
// tile = 32x32. Region layout (tiles): qkv 3072 | proj 1024 | fc 4096 | pr2 4096
__global__ __launch_bounds__(256) void cvt_all_kernel(const float* __restrict__ W0,
                                                      const float* __restrict__ W1,
                                                      const float* __restrict__ W2,
                                                      const float* __restrict__ W3,
                                                      __half* __restrict__ T0,
                                                      __half* __restrict__ T1,
                                                      __half* __restrict__ T2,
                                                      __half* __restrict__ T3)
{
    __shared__ float tile[32][33];
    int t = blockIdx.x;
    const float* W; __half* Wt; int K, N, local;
    if (t < 3072)      { W = W0; Wt = T0; K = 1024; N = 3072; local = t; }
    else if (t < 4096) { W = W1; Wt = T1; K = 1024; N = 1024; local = t - 3072; }
    else if (t < 8192) { W = W2; Wt = T2; K = 1024; N = 4096; local = t - 4096; }
    else               { W = W3; Wt = T3; K = 4096; N = 1024; local = t - 8192; }
    int nx = N >> 5;
    int n0 = (local % nx) * 32, k0 = (local / nx) * 32;
    int tx = threadIdx.x & 31, ty = threadIdx.x >> 5;
    #pragma unroll
    for (int j = 0; j < 4; j++) {
        int k = k0 + ty + j * 8;
        tile[ty + j * 8][tx] = W[(size_t)k * N + n0 + tx];
    }
    __syncthreads();
    #pragma unroll
    for (int j = 0; j < 4; j++) {
        int n = n0 + ty + j * 8;
        Wt[(size_t)n * K + k0 + tx] = __float2half(tile[tx][ty + j * 8]);
    }
}

// ---------------- LayerNorm: warp-per-row, no block sync ----------------
// 256 thr = 8 warps = 8 rows/block. Lane owns 8 float4 (32 elems).
__global__ __launch_bounds__(256) void ln_kernel(const float* __restrict__ x,
                                                 const float* __restrict__ w,
                                                 const float* __restrict__ b,
                                                 float* __restrict__ y,
                                                 __half* __restrict__ yh)
{
    int wid = threadIdx.x >> 5, lane = threadIdx.x & 31;
    int row = blockIdx.x * 8 + wid;
    const float4* xr = (const float4*)(x + (size_t)row * D_MODEL);
    float4 v[8];
    float s = 0.0f, sq = 0.0f;
    #pragma unroll
    for (int j = 0; j < 8; j++) {
        v[j] = xr[lane + j * 32];
        s  += v[j].x + v[j].y + v[j].z + v[j].w;
        sq += v[j].x*v[j].x + v[j].y*v[j].y + v[j].z*v[j].z + v[j].w*v[j].w;
    }
    #pragma unroll
    for (int o = 16; o > 0; o >>= 1) {
        s  += __shfl_xor_sync(0xFFFFFFFFu, s, o);
        sq += __shfl_xor_sync(0xFFFFFFFFu, sq, o);
    }
    float mu = s * (1.0f / D_MODEL);
    float rstd = rsqrtf(sq * (1.0f / D_MODEL) - mu * mu + 1e-5f);
    float4* yr = (float4*)(y + (size_t)row * D_MODEL);
    uint2* yhr = (uint2*)(yh + (size_t)row * D_MODEL);
    #pragma unroll
    for (int j = 0; j < 8; j++) {
        int idx = lane + j * 32;
        float4 wv = ((const float4*)w)[idx];
        float4 bv = ((const float4*)b)[idx];
        float4 r;
        r.x = (v[j].x - mu) * rstd * wv.x + bv.x;
        r.y = (v[j].y - mu) * rstd * wv.y + bv.y;
        r.z = (v[j].z - mu) * rstd * wv.z + bv.z;
        r.w = (v[j].w - mu) * rstd * wv.w + bv.w;
        yr[idx] = r;
        __half2 h0 = __floats2half2_rn(r.x, r.y);
        __half2 h1 = __floats2half2_rn(r.z, r.w);
        uint2 u = { *(uint32_t*)&h0, *(uint32_t*)&h1 };
        yhr[idx] = u;
    }
}

// ---------------- MMA helpers ----------------
__device__ __forceinline__ void mma_f16(float* d, const uint32_t* a, const uint32_t* b) {
    asm volatile(
        "mma.sync.aligned.m16n8k16.row.col.f32.f16.f16.f32 "
        "{%0,%1,%2,%3}, {%4,%5,%6,%7}, {%8,%9}, {%0,%1,%2,%3};\n"
        : "+f"(d[0]), "+f"(d[1]), "+f"(d[2]), "+f"(d[3])
        : "r"(a[0]), "r"(a[1]), "r"(a[2]), "r"(a[3]), "r"(b[0]), "r"(b[1]));
}
__device__ __forceinline__ void ldsm_x4(uint32_t& r0, uint32_t& r1, uint32_t& r2, uint32_t& r3,
                                        uint32_t addr) {
    asm volatile("ldmatrix.sync.aligned.m8n8.x4.shared.b16 {%0,%1,%2,%3}, [%4];"
                 : "=r"(r0), "=r"(r1), "=r"(r2), "=r"(r3) : "r"(addr));
}
__device__ __forceinline__ void ldsm_x4_t(uint32_t& r0, uint32_t& r1, uint32_t& r2, uint32_t& r3,
                                          uint32_t addr) {
    asm volatile("ldmatrix.sync.aligned.m8n8.x4.trans.shared.b16 {%0,%1,%2,%3}, [%4];"
                 : "=r"(r0), "=r"(r1), "=r"(r2), "=r"(r3) : "r"(addr));
}
__device__ __forceinline__ void cp16(uint32_t dst, const void* src) {
    asm volatile("cp.async.cg.shared.global [%0], [%1], 16;\n" :: "r"(dst), "l"(src));
}
__device__ __forceinline__ void cp_commit() {
    asm volatile("cp.async.commit_group;\n");
}
template <int N>
__device__ __forceinline__ void cp_wait() {
    asm volatile("cp.async.wait_group %0;\n" :: "n"(N));
}

// ---------------- fp16 GEMM: 256 thr, warp 64x32, BK=64, 3-stage, one sync ----------------
#define EPI_BIAS      0
#define EPI_BIAS_GELU 1
#define EPI_BIAS_RES  2

#define ROW_BYTES 144
#define STAGE_BYTES (128 * ROW_BYTES)
#define GEMM_STAGES 3
#define GEMM_SMEM_BYTES (GEMM_STAGES * 2 * STAGE_BYTES)   // 110592

template <int EPI>
__global__ __launch_bounds__(256, 2) void mma_gemm(const __half* __restrict__ A,
                                                   const __half* __restrict__ Bt,
                                                   const float* __restrict__ bias,
                                                   const float* __restrict__ res,
                                                   void* __restrict__ Cv,
                                                   int M, int N, int K)
{
    extern __shared__ uint8_t smem8[];
    uint32_t sbA = (uint32_t)__cvta_generic_to_shared(smem8);
    uint32_t sbB = sbA + GEMM_STAGES * STAGE_BYTES;

    int tid = threadIdx.x;
    int wid = tid >> 5, lane = tid & 31;
    int gid = lane >> 2, tig = lane & 3;
    int warp_m = wid & 1, warp_n = wid >> 1;
    int bx = blockIdx.x, by = blockIdx.y;

    const __half* Asrc[4];
    const __half* Bsrc[4];
    uint32_t Adst[4], Bdst[4];
    #pragma unroll
    for (int j = 0; j < 4; j++) {
        int q = tid + j * 256;
        int r = q >> 3, c = q & 7;
        Asrc[j] = A  + (size_t)(by * 128 + r) * K + c * 8;
        Bsrc[j] = Bt + (size_t)(bx * 128 + r) * K + c * 8;
        Adst[j] = sbA + r * ROW_BYTES + c * 16;
        Bdst[j] = sbB + r * ROW_BYTES + c * 16;
    }

    uint32_t a_lm = sbA + (warp_m * 64 + (lane & 15)) * ROW_BYTES + ((lane >> 4) * 16);
    uint32_t b_lm = sbB + (warp_n * 32 + (lane & 15)) * ROW_BYTES + ((lane >> 4) * 16);

    float acc[4][4][4];
    #pragma unroll
    for (int mt = 0; mt < 4; mt++)
        #pragma unroll
        for (int nt = 0; nt < 4; nt++)
            #pragma unroll
            for (int r = 0; r < 4; r++) acc[mt][nt][r] = 0.0f;

    int nIter = K >> 6;
    #pragma unroll
    for (int s = 0; s < 2; s++) {
        #pragma unroll
        for (int j = 0; j < 4; j++) {
            cp16(Adst[j] + s * STAGE_BYTES, Asrc[j] + s * 64);
            cp16(Bdst[j] + s * STAGE_BYTES, Bsrc[j] + s * 64);
        }
        cp_commit();
    }

    for (int it = 0; it < nIter; it++) {
        cp_wait<1>();
        __syncthreads();
        if (it + 2 < nIter) {
            int sb = (it + 2) % GEMM_STAGES;
            int k0 = (it + 2) << 6;
            #pragma unroll
            for (int j = 0; j < 4; j++) {
                cp16(Adst[j] + sb * STAGE_BYTES, Asrc[j] + k0);
                cp16(Bdst[j] + sb * STAGE_BYTES, Bsrc[j] + k0);
            }
        }
        cp_commit();

        int buf = it % GEMM_STAGES;
        uint32_t abase = a_lm + buf * STAGE_BYTES;
        uint32_t bbase = b_lm + buf * STAGE_BYTES;
        #pragma unroll
        for (int ks = 0; ks < 4; ks++) {
            uint32_t af[4][4], bf[4][2];
            #pragma unroll
            for (int mt = 0; mt < 4; mt++)
                ldsm_x4(af[mt][0], af[mt][1], af[mt][2], af[mt][3],
                        abase + mt * 16 * ROW_BYTES + ks * 32);
            #pragma unroll
            for (int p = 0; p < 2; p++)
                ldsm_x4(bf[2*p][0], bf[2*p+1][0], bf[2*p][1], bf[2*p+1][1],
                        bbase + p * 16 * ROW_BYTES + ks * 32);
            #pragma unroll
            for (int mt = 0; mt < 4; mt++)
                #pragma unroll
                for (int nt = 0; nt < 4; nt++)
                    mma_f16(acc[mt][nt], af[mt], bf[nt]);
        }
    }

    #pragma unroll
    for (int mt = 0; mt < 4; mt++) {
        #pragma unroll
        for (int nt = 0; nt < 4; nt++) {
            int row0 = by * 128 + warp_m * 64 + mt * 16 + gid;
            int col  = bx * 128 + warp_n * 32 + nt * 8 + tig * 2;
            float b0 = bias[col], b1 = bias[col + 1];
            #pragma unroll
            for (int half_i = 0; half_i < 2; half_i++) {
                int row = row0 + half_i * 8;
                float v0 = acc[mt][nt][half_i * 2 + 0] + b0;
                float v1 = acc[mt][nt][half_i * 2 + 1] + b1;
                if (EPI == EPI_BIAS_GELU) {
                    v0 = 0.5f * v0 * (1.0f + erff(v0 * 0.70710678118654752f));
                    v1 = 0.5f * v1 * (1.0f + erff(v1 * 0.70710678118654752f));
                    __half2 hv = __floats2half2_rn(v0, v1);
                    *(__half2*)((__half*)Cv + (size_t)row * N + col) = hv;
                } else {
                    if (EPI == EPI_BIAS_RES) {
                        float2 rv = *(const float2*)(res + (size_t)row * N + col);
                        v0 += rv.x; v1 += rv.y;
                    }
                    float2 o2 = { v0, v1 };
                    *(float2*)((float*)Cv + (size_t)row * N + col) = o2;
                }
            }
        }
    }
}

// ---------------- Flash attention: fp16 MMA + ldmatrix (round-10 version) ----------------
#define AROW 144
#define ATTN_SMEM (3 * 64 * AROW)

__global__ __launch_bounds__(128) void attn_kernel(const float* __restrict__ qkv,
                                                   __half* __restrict__ out)
{
    extern __shared__ uint8_t smem8[];
    uint32_t sb = (uint32_t)__cvta_generic_to_shared(smem8);
    uint8_t* QP = smem8;
    uint8_t* Ks = smem8 + 64 * AROW;
    uint8_t* Vs = smem8 + 2 * 64 * AROW;
    uint32_t sbQP = sb, sbK = sb + 64 * AROW, sbV = sb + 2 * 64 * AROW;

    int bh = blockIdx.y;
    int b = bh >> 4, h = bh & 15;
    int q0 = blockIdx.x * 64;
    int tid = threadIdx.x;
    int wid = tid >> 5, lane = tid & 31;
    int gid = lane >> 2, tig = lane & 3;
    int m0 = wid * 16;

    // load Q (scaled, fp16)
    for (int i = tid; i < 64 * 16; i += 128) {
        int r = i >> 4, c = (i & 15) * 4;
        float4 v = *(const float4*)(qkv + (size_t)(b * SEQ + q0 + r) * 3 * D_MODEL + h * HD + c);
        __half2 h0 = __floats2half2_rn(v.x * 0.125f, v.y * 0.125f);
        __half2 h1 = __floats2half2_rn(v.z * 0.125f, v.w * 0.125f);
        uint2 u = { *(uint32_t*)&h0, *(uint32_t*)&h1 };
        *(uint2*)(QP + r * AROW + c * 2) = u;
    }
    __syncthreads();

    uint32_t q_lm = sbQP + (m0 + (lane & 15)) * AROW + ((lane >> 4) * 16);
    uint32_t qa[4][4];
    #pragma unroll
    for (int ks = 0; ks < 4; ks++)
        ldsm_x4(qa[ks][0], qa[ks][1], qa[ks][2], qa[ks][3], q_lm + ks * 32);
    __syncthreads();

    uint32_t k_lm = sbK + ((lane & 15)) * AROW + ((lane >> 4) * 16);
    uint32_t p_lm = q_lm;

    float o[8][4];
    #pragma unroll
    for (int nt = 0; nt < 8; nt++)
        #pragma unroll
        for (int j = 0; j < 4; j++) o[nt][j] = 0.0f;
    float ms0 = -3.0e38f, ms1 = -3.0e38f, ls0 = 0.0f, ls1 = 0.0f;

    for (int kt = 0; kt <= q0; kt += 64) {
        for (int i = tid; i < 64 * 16; i += 128) {
            int r = i >> 4, c = (i & 15) * 4;
            const float* base = qkv + (size_t)(b * SEQ + kt + r) * 3 * D_MODEL + h * HD + c;
            float4 kv = *(const float4*)(base + D_MODEL);
            float4 vv = *(const float4*)(base + 2 * D_MODEL);
            __half2 k0h = __floats2half2_rn(kv.x, kv.y);
            __half2 k1h = __floats2half2_rn(kv.z, kv.w);
            __half2 v0h = __floats2half2_rn(vv.x, vv.y);
            __half2 v1h = __floats2half2_rn(vv.z, vv.w);
            uint2 uk = { *(uint32_t*)&k0h, *(uint32_t*)&k1h };
            uint2 uv = { *(uint32_t*)&v0h, *(uint32_t*)&v1h };
            *(uint2*)(Ks + r * AROW + c * 2) = uk;
            *(uint2*)(Vs + r * AROW + c * 2) = uv;
        }
        __syncthreads();

        float sc[8][4];
        #pragma unroll
        for (int nt = 0; nt < 8; nt++)
            #pragma unroll
            for (int j = 0; j < 4; j++) sc[nt][j] = 0.0f;
        #pragma unroll
        for (int ks = 0; ks < 4; ks++) {
            uint32_t bf[8][2];
            #pragma unroll
            for (int p = 0; p < 4; p++)
                ldsm_x4(bf[2*p][0], bf[2*p+1][0], bf[2*p][1], bf[2*p+1][1],
                        k_lm + p * 16 * AROW + ks * 32);
            #pragma unroll
            for (int nt = 0; nt < 8; nt++)
                mma_f16(sc[nt], qa[ks], bf[nt]);
        }

        if (kt == q0) {
            int r0 = m0 + gid, r1 = r0 + 8;
            #pragma unroll
            for (int nt = 0; nt < 8; nt++) {
                int c0 = nt * 8 + tig * 2;
                if (c0     > r0) sc[nt][0] = -3.0e38f;
                if (c0 + 1 > r0) sc[nt][1] = -3.0e38f;
                if (c0     > r1) sc[nt][2] = -3.0e38f;
                if (c0 + 1 > r1) sc[nt][3] = -3.0e38f;
            }
        }

        float tm0 = -3.0e38f, tm1 = -3.0e38f;
        #pragma unroll
        for (int nt = 0; nt < 8; nt++) {
            tm0 = fmaxf(tm0, fmaxf(sc[nt][0], sc[nt][1]));
            tm1 = fmaxf(tm1, fmaxf(sc[nt][2], sc[nt][3]));
        }
        #pragma unroll
        for (int off = 1; off <= 2; off <<= 1) {
            tm0 = fmaxf(tm0, __shfl_xor_sync(0xFFFFFFFFu, tm0, off));
            tm1 = fmaxf(tm1, __shfl_xor_sync(0xFFFFFFFFu, tm1, off));
        }
        float mn0 = fmaxf(ms0, tm0), mn1 = fmaxf(ms1, tm1);
        float cc0 = __expf(ms0 - mn0), cc1 = __expf(ms1 - mn1);
        ms0 = mn0; ms1 = mn1;
        float ps0 = 0.0f, ps1 = 0.0f;
        #pragma unroll
        for (int nt = 0; nt < 8; nt++) {
            sc[nt][0] = __expf(sc[nt][0] - mn0); ps0 += sc[nt][0];
            sc[nt][1] = __expf(sc[nt][1] - mn0); ps0 += sc[nt][1];
            sc[nt][2] = __expf(sc[nt][2] - mn1); ps1 += sc[nt][2];
            sc[nt][3] = __expf(sc[nt][3] - mn1); ps1 += sc[nt][3];
        }
        #pragma unroll
        for (int off = 1; off <= 2; off <<= 1) {
            ps0 += __shfl_xor_sync(0xFFFFFFFFu, ps0, off);
            ps1 += __shfl_xor_sync(0xFFFFFFFFu, ps1, off);
        }
        ls0 = ls0 * cc0 + ps0;
        ls1 = ls1 * cc1 + ps1;
        #pragma unroll
        for (int nt = 0; nt < 8; nt++) {
            o[nt][0] *= cc0; o[nt][1] *= cc0;
            o[nt][2] *= cc1; o[nt][3] *= cc1;
        }

        __syncwarp();
        #pragma unroll
        for (int nt = 0; nt < 8; nt++) {
            int c0 = nt * 8 + tig * 2;
            __half2 p0 = __floats2half2_rn(sc[nt][0], sc[nt][1]);
            __half2 p1 = __floats2half2_rn(sc[nt][2], sc[nt][3]);
            *(__half2*)(QP + (m0 + gid    ) * AROW + c0 * 2) = p0;
            *(__half2*)(QP + (m0 + gid + 8) * AROW + c0 * 2) = p1;
        }
        __syncwarp();

        #pragma unroll
        for (int ks = 0; ks < 4; ks++) {
            uint32_t pf[4];
            ldsm_x4(pf[0], pf[1], pf[2], pf[3], p_lm + ks * 32);
            uint32_t v_base = sbV + (ks * 16 + (lane & 15)) * AROW + ((lane >> 4) * 16);
            #pragma unroll
            for (int p = 0; p < 4; p++) {
                uint32_t bf[2][2];
                ldsm_x4_t(bf[0][0], bf[0][1], bf[1][0], bf[1][1], v_base + p * 32);
                mma_f16(o[2*p    ], pf, bf[0]);
                mma_f16(o[2*p + 1], pf, bf[1]);
            }
        }
        __syncthreads();
    }

    float inv0 = 1.0f / ls0, inv1 = 1.0f / ls1;
    int row0 = b * SEQ + q0 + m0 + gid;
    int row1 = row0 + 8;
    #pragma unroll
    for (int nt = 0; nt < 8; nt++) {
        int col = h * HD + nt * 8 + tig * 2;
        *(__half2*)(out + (size_t)row0 * D_MODEL + col) = __floats2half2_rn(o[nt][0] * inv0, o[nt][1] * inv0);
        *(__half2*)(out + (size_t)row1 * D_MODEL + col) = __floats2half2_rn(o[nt][2] * inv1, o[nt][3] * inv1);
    }
}

// ---------------- launch ----------------
extern "C" void kernel_launch(void* const* d_in, const int* in_sizes, int n_in,
                              void* d_out, int out_size)
{
    const float* x          = (const float*)d_in[0];
    const float* ln1_w      = (const float*)d_in[1];
    const float* ln1_b      = (const float*)d_in[2];
    const float* qkv_w      = (const float*)d_in[3];
    const float* qkv_b      = (const float*)d_in[4];
    const float* attn_out_w = (const float*)d_in[5];
    const float* attn_out_b = (const float*)d_in[6];
    const float* ln2_w      = (const float*)d_in[7];
    const float* ln2_b      = (const float*)d_in[8];
    const float* c_fc_w     = (const float*)d_in[9];
    const float* c_fc_b     = (const float*)d_in[10];
    const float* c_proj_w   = (const float*)d_in[11];
    const float* c_proj_b   = (const float*)d_in[12];
    float* out = (float*)d_out;

    float *XN, *QKV, *H, *HN;
    __half *XNh, *Oh, *HNh, *Gh, *Wqkv, *Wproj, *Wfc, *Wpr2;
    cudaGetSymbolAddress((void**)&XN,   g_XN);
    cudaGetSymbolAddress((void**)&XNh,  g_XNh);
    cudaGetSymbolAddress((void**)&QKV,  g_QKV);
    cudaGetSymbolAddress((void**)&Oh,   g_Oh);
    cudaGetSymbolAddress((void**)&H,    g_H);
    cudaGetSymbolAddress((void**)&HN,   g_HN);
    cudaGetSymbolAddress((void**)&HNh,  g_HNh);
    cudaGetSymbolAddress((void**)&Gh,   g_Gh);
    cudaGetSymbolAddress((void**)&Wqkv, g_Wqkv);
    cudaGetSymbolAddress((void**)&Wproj,g_Wproj);
    cudaGetSymbolAddress((void**)&Wfc,  g_Wfc);
    cudaGetSymbolAddress((void**)&Wpr2, g_Wpr2);

    cudaFuncSetAttribute(mma_gemm<EPI_BIAS>,      cudaFuncAttributeMaxDynamicSharedMemorySize, GEMM_SMEM_BYTES);
    cudaFuncSetAttribute(mma_gemm<EPI_BIAS_GELU>, cudaFuncAttributeMaxDynamicSharedMemorySize, GEMM_SMEM_BYTES);
    cudaFuncSetAttribute(mma_gemm<EPI_BIAS_RES>,  cudaFuncAttributeMaxDynamicSharedMemorySize, GEMM_SMEM_BYTES);
    cudaFuncSetAttribute(attn_kernel,             cudaFuncAttributeMaxDynamicSharedMemorySize, ATTN_SMEM);

    // all four weight transposes in one launch
    cvt_all_kernel<<<12288, 256>>>(qkv_w, attn_out_w, c_fc_w, c_proj_w,
                                   Wqkv, Wproj, Wfc, Wpr2);

    ln_kernel<<<ROWS / 8, 256>>>(x, ln1_w, ln1_b, XN, XNh);

    mma_gemm<EPI_BIAS><<<dim3(3 * D_MODEL / 128, ROWS / 128), 256, GEMM_SMEM_BYTES>>>(
        XNh, Wqkv, qkv_b, nullptr, QKV, ROWS, 3 * D_MODEL, D_MODEL);

    attn_kernel<<<dim3(SEQ / 64, BATCH * NHEAD), 128, ATTN_SMEM>>>(QKV, Oh);

    mma_gemm<EPI_BIAS_RES><<<dim3(D_MODEL / 128, ROWS / 128), 256, GEMM_SMEM_BYTES>>>(
        Oh, Wproj, attn_out_b, XN, H, ROWS, D_MODEL, D_MODEL);

    ln_kernel<<<ROWS / 8, 256>>>(H, ln2_w, ln2_b, HN, HNh);

    mma_gemm<EPI_BIAS_GELU><<<dim3(4 * D_MODEL / 128, ROWS / 128), 256, GEMM_SMEM_BYTES>>>(
        HNh, Wfc, c_fc_b, nullptr, Gh, ROWS, 4 * D_MODEL, D_MODEL);

    mma_gemm<EPI_BIAS_RES><<<dim3(D_MODEL / 128, ROWS / 128), 256, GEMM_SMEM_BYTES>>>(
        Gh, Wpr2, c_proj_b, HN, out, ROWS, D_MODEL, 4 * D_MODEL);
}

// round 14
// speedup vs baseline: 1.0502x; 1.0166x over previous
#include <cuda_runtime.h>
#include <cuda_fp16.h>
#include <math.h>
#include <stdint.h>

#define D_MODEL 1024
#define SEQ 2048
#define BATCH 2
#define NHEAD 16
#define HD 64
#define ROWS (BATCH*SEQ)   // 4096

// ---------------- scratch ----------------
__device__ float  g_XN [ROWS * D_MODEL];
__device__ __half g_XNh[ROWS * D_MODEL];
__device__ __half g_QKVh[ROWS * 3 * D_MODEL];   // fp16, Q pre-scaled by 0.125
__device__ __half g_Oh [ROWS * D_MODEL];
__device__ float  g_H  [ROWS * D_MODEL];
__device__ float  g_HN [ROWS * D_MODEL];
__device__ __half g_HNh[ROWS * D_MODEL];
__device__ __half g_Gh [ROWS * 4 * D_MODEL];
__device__ __half g_Wqkv [3 * D_MODEL * D_MODEL];
__device__ __half g_Wproj[D_MODEL * D_MODEL];
__device__ __half g_Wfc  [4 * D_MODEL * D_MODEL];
__device__ __half g_Wpr2 [D_MODEL * 4 * D_MODEL];

// ---------------- fused weight transpose (one launch) ----------------
__global__ __launch_bounds__(256) void cvt_all_kernel(const float* __restrict__ W0,
                                                      const float* __restrict__ W1,
                                                      const float* __restrict__ W2,
                                                      const float* __restrict__ W3,
                                                      __half* __restrict__ T0,
                                                      __half* __restrict__ T1,
                                                      __half* __restrict__ T2,
                                                      __half* __restrict__ T3)
{
    __shared__ float tile[32][33];
    int t = blockIdx.x;
    const float* W; __half* Wt; int K, N, local;
    if (t < 3072)      { W = W0; Wt = T0; K = 1024; N = 3072; local = t; }
    else if (t < 4096) { W = W1; Wt = T1; K = 1024; N = 1024; local = t - 3072; }
    else if (t < 8192) { W = W2; Wt = T2; K = 1024; N = 4096; local = t - 4096; }
    else               { W = W3; Wt = T3; K = 4096; N = 1024; local = t - 8192; }
    int nx = N >> 5;
    int n0 = (local % nx) * 32, k0 = (local / nx) * 32;
    int tx = threadIdx.x & 31, ty = threadIdx.x >> 5;
    #pragma unroll
    for (int j = 0; j < 4; j++) {
        int k = k0 + ty + j * 8;
        tile[ty + j * 8][tx] = W[(size_t)k * N + n0 + tx];
    }
    __syncthreads();
    #pragma unroll
    for (int j = 0; j < 4; j++) {
        int n = n0 + ty + j * 8;
        Wt[(size_t)n * K + k0 + tx] = __float2half(tile[tx][ty + j * 8]);
    }
}

// ---------------- LayerNorm: warp-per-row ----------------
__global__ __launch_bounds__(256) void ln_kernel(const float* __restrict__ x,
                                                 const float* __restrict__ w,
                                                 const float* __restrict__ b,
                                                 float* __restrict__ y,
                                                 __half* __restrict__ yh)
{
    int wid = threadIdx.x >> 5, lane = threadIdx.x & 31;
    int row = blockIdx.x * 8 + wid;
    const float4* xr = (const float4*)(x + (size_t)row * D_MODEL);
    float4 v[8];
    float s = 0.0f, sq = 0.0f;
    #pragma unroll
    for (int j = 0; j < 8; j++) {
        v[j] = xr[lane + j * 32];
        s  += v[j].x + v[j].y + v[j].z + v[j].w;
        sq += v[j].x*v[j].x + v[j].y*v[j].y + v[j].z*v[j].z + v[j].w*v[j].w;
    }
    #pragma unroll
    for (int o = 16; o > 0; o >>= 1) {
        s  += __shfl_xor_sync(0xFFFFFFFFu, s, o);
        sq += __shfl_xor_sync(0xFFFFFFFFu, sq, o);
    }
    float mu = s * (1.0f / D_MODEL);
    float rstd = rsqrtf(sq * (1.0f / D_MODEL) - mu * mu + 1e-5f);
    float4* yr = (float4*)(y + (size_t)row * D_MODEL);
    uint2* yhr = (uint2*)(yh + (size_t)row * D_MODEL);
    #pragma unroll
    for (int j = 0; j < 8; j++) {
        int idx = lane + j * 32;
        float4 wv = ((const float4*)w)[idx];
        float4 bv = ((const float4*)b)[idx];
        float4 r;
        r.x = (v[j].x - mu) * rstd * wv.x + bv.x;
        r.y = (v[j].y - mu) * rstd * wv.y + bv.y;
        r.z = (v[j].z - mu) * rstd * wv.z + bv.z;
        r.w = (v[j].w - mu) * rstd * wv.w + bv.w;
        yr[idx] = r;
        __half2 h0 = __floats2half2_rn(r.x, r.y);
        __half2 h1 = __floats2half2_rn(r.z, r.w);
        uint2 u = { *(uint32_t*)&h0, *(uint32_t*)&h1 };
        yhr[idx] = u;
    }
}

// ---------------- MMA helpers ----------------
__device__ __forceinline__ void mma_f16(float* d, const uint32_t* a, const uint32_t* b) {
    asm volatile(
        "mma.sync.aligned.m16n8k16.row.col.f32.f16.f16.f32 "
        "{%0,%1,%2,%3}, {%4,%5,%6,%7}, {%8,%9}, {%0,%1,%2,%3};\n"
        : "+f"(d[0]), "+f"(d[1]), "+f"(d[2]), "+f"(d[3])
        : "r"(a[0]), "r"(a[1]), "r"(a[2]), "r"(a[3]), "r"(b[0]), "r"(b[1]));
}
__device__ __forceinline__ void ldsm_x4(uint32_t& r0, uint32_t& r1, uint32_t& r2, uint32_t& r3,
                                        uint32_t addr) {
    asm volatile("ldmatrix.sync.aligned.m8n8.x4.shared.b16 {%0,%1,%2,%3}, [%4];"
                 : "=r"(r0), "=r"(r1), "=r"(r2), "=r"(r3) : "r"(addr));
}
__device__ __forceinline__ void ldsm_x4_t(uint32_t& r0, uint32_t& r1, uint32_t& r2, uint32_t& r3,
                                          uint32_t addr) {
    asm volatile("ldmatrix.sync.aligned.m8n8.x4.trans.shared.b16 {%0,%1,%2,%3}, [%4];"
                 : "=r"(r0), "=r"(r1), "=r"(r2), "=r"(r3) : "r"(addr));
}
__device__ __forceinline__ void cp16(uint32_t dst, const void* src) {
    asm volatile("cp.async.cg.shared.global [%0], [%1], 16;\n" :: "r"(dst), "l"(src));
}
__device__ __forceinline__ void cp_commit() {
    asm volatile("cp.async.commit_group;\n");
}
template <int N>
__device__ __forceinline__ void cp_wait() {
    asm volatile("cp.async.wait_group %0;\n" :: "n"(N));
}

// ---------------- fp16 GEMM (round-10 proven config) ----------------
#define EPI_BIAS      0
#define EPI_BIAS_GELU 1
#define EPI_BIAS_RES  2
#define EPI_BIAS_QKV  3

#define ROW_BYTES 144
#define STAGE_BYTES (128 * ROW_BYTES)
#define GEMM_STAGES 3
#define GEMM_SMEM_BYTES (GEMM_STAGES * 2 * STAGE_BYTES)   // 110592

template <int EPI>
__global__ __launch_bounds__(256, 2) void mma_gemm(const __half* __restrict__ A,
                                                   const __half* __restrict__ Bt,
                                                   const float* __restrict__ bias,
                                                   const float* __restrict__ res,
                                                   void* __restrict__ Cv,
                                                   int M, int N, int K)
{
    extern __shared__ uint8_t smem8[];
    uint32_t sbA = (uint32_t)__cvta_generic_to_shared(smem8);
    uint32_t sbB = sbA + GEMM_STAGES * STAGE_BYTES;

    int tid = threadIdx.x;
    int wid = tid >> 5, lane = tid & 31;
    int gid = lane >> 2, tig = lane & 3;
    int warp_m = wid & 1, warp_n = wid >> 1;
    int bx = blockIdx.x, by = blockIdx.y;

    const __half* Asrc[4];
    const __half* Bsrc[4];
    uint32_t Adst[4], Bdst[4];
    #pragma unroll
    for (int j = 0; j < 4; j++) {
        int q = tid + j * 256;
        int r = q >> 3, c = q & 7;
        Asrc[j] = A  + (size_t)(by * 128 + r) * K + c * 8;
        Bsrc[j] = Bt + (size_t)(bx * 128 + r) * K + c * 8;
        Adst[j] = sbA + r * ROW_BYTES + c * 16;
        Bdst[j] = sbB + r * ROW_BYTES + c * 16;
    }

    uint32_t a_lm = sbA + (warp_m * 64 + (lane & 15)) * ROW_BYTES + ((lane >> 4) * 16);
    uint32_t b_lm = sbB + (warp_n * 32 + (lane & 15)) * ROW_BYTES + ((lane >> 4) * 16);

    float acc[4][4][4];
    #pragma unroll
    for (int mt = 0; mt < 4; mt++)
        #pragma unroll
        for (int nt = 0; nt < 4; nt++)
            #pragma unroll
            for (int r = 0; r < 4; r++) acc[mt][nt][r] = 0.0f;

    int nIter = K >> 6;
    #pragma unroll
    for (int s = 0; s < 2; s++) {
        #pragma unroll
        for (int j = 0; j < 4; j++) {
            cp16(Adst[j] + s * STAGE_BYTES, Asrc[j] + s * 64);
            cp16(Bdst[j] + s * STAGE_BYTES, Bsrc[j] + s * 64);
        }
        cp_commit();
    }

    for (int it = 0; it < nIter; it++) {
        cp_wait<1>();
        __syncthreads();
        if (it + 2 < nIter) {
            int sb = (it + 2) % GEMM_STAGES;
            int k0 = (it + 2) << 6;
            #pragma unroll
            for (int j = 0; j < 4; j++) {
                cp16(Adst[j] + sb * STAGE_BYTES, Asrc[j] + k0);
                cp16(Bdst[j] + sb * STAGE_BYTES, Bsrc[j] + k0);
            }
        }
        cp_commit();

        int buf = it % GEMM_STAGES;
        uint32_t abase = a_lm + buf * STAGE_BYTES;
        uint32_t bbase = b_lm + buf * STAGE_BYTES;
        #pragma unroll
        for (int ks = 0; ks < 4; ks++) {
            uint32_t af[4][4], bf[4][2];
            #pragma unroll
            for (int mt = 0; mt < 4; mt++)
                ldsm_x4(af[mt][0], af[mt][1], af[mt][2], af[mt][3],
                        abase + mt * 16 * ROW_BYTES + ks * 32);
            #pragma unroll
            for (int p = 0; p < 2; p++)
                ldsm_x4(bf[2*p][0], bf[2*p+1][0], bf[2*p][1], bf[2*p+1][1],
                        bbase + p * 16 * ROW_BYTES + ks * 32);
            #pragma unroll
            for (int mt = 0; mt < 4; mt++)
                #pragma unroll
                for (int nt = 0; nt < 4; nt++)
                    mma_f16(acc[mt][nt], af[mt], bf[nt]);
        }
    }

    #pragma unroll
    for (int mt = 0; mt < 4; mt++) {
        #pragma unroll
        for (int nt = 0; nt < 4; nt++) {
            int row0 = by * 128 + warp_m * 64 + mt * 16 + gid;
            int col  = bx * 128 + warp_n * 32 + nt * 8 + tig * 2;
            float b0 = bias[col], b1 = bias[col + 1];
            #pragma unroll
            for (int half_i = 0; half_i < 2; half_i++) {
                int row = row0 + half_i * 8;
                float v0 = acc[mt][nt][half_i * 2 + 0] + b0;
                float v1 = acc[mt][nt][half_i * 2 + 1] + b1;
                if (EPI == EPI_BIAS_QKV) {
                    if (col < D_MODEL) { v0 *= 0.125f; v1 *= 0.125f; }
                    __half2 hv = __floats2half2_rn(v0, v1);
                    *(__half2*)((__half*)Cv + (size_t)row * N + col) = hv;
                } else if (EPI == EPI_BIAS_GELU) {
                    v0 = 0.5f * v0 * (1.0f + erff(v0 * 0.70710678118654752f));
                    v1 = 0.5f * v1 * (1.0f + erff(v1 * 0.70710678118654752f));
                    __half2 hv = __floats2half2_rn(v0, v1);
                    *(__half2*)((__half*)Cv + (size_t)row * N + col) = hv;
                } else {
                    if (EPI == EPI_BIAS_RES) {
                        float2 rv = *(const float2*)(res + (size_t)row * N + col);
                        v0 += rv.x; v1 += rv.y;
                    }
                    float2 o2 = { v0, v1 };
                    *(float2*)((float*)Cv + (size_t)row * N + col) = o2;
                }
            }
        }
    }
}

// ---------------- Flash attention: 128 queries/block, 8 warps, cp.async K/V ----------------
#define AROW 144
#define KV_STAGE (64 * AROW)                    // 9216 per matrix per stage
#define ATTN_STAGES 3
#define ATTN_SMEM (128 * AROW + 2 * ATTN_STAGES * KV_STAGE)   // 18432 + 55296 = 73728

__global__ __launch_bounds__(256, 2) void attn_kernel(const __half* __restrict__ qkv,
                                                      __half* __restrict__ out)
{
    extern __shared__ uint8_t smem8[];
    uint32_t sb = (uint32_t)__cvta_generic_to_shared(smem8);
    uint8_t* QP = smem8;
    uint32_t sbQP = sb;
    uint32_t sbK = sb + 128 * AROW;
    uint32_t sbV = sbK + ATTN_STAGES * KV_STAGE;

    int bh = blockIdx.y;
    int b = bh >> 4, h = bh & 15;
    int q0 = blockIdx.x * 128;
    int tid = threadIdx.x;
    int wid = tid >> 5, lane = tid & 31;
    int gid = lane >> 2, tig = lane & 3;
    int m0 = wid * 16;   // warp's query rows q0+m0 .. q0+m0+15

    // load Q (fp16, pre-scaled): 128 rows x 8 x 16B
    for (int i = tid; i < 128 * 8; i += 256) {
        int r = i >> 3, c = i & 7;
        *(uint4*)(QP + r * AROW + c * 16) =
            *(const uint4*)(qkv + (size_t)(b * SEQ + q0 + r) * 3 * D_MODEL + h * HD + c * 8);
    }
    __syncthreads();

    uint32_t q_lm = sbQP + (m0 + (lane & 15)) * AROW + ((lane >> 4) * 16);
    uint32_t qa[4][4];
    #pragma unroll
    for (int ks = 0; ks < 4; ks++)
        ldsm_x4(qa[ks][0], qa[ks][1], qa[ks][2], qa[ks][3], q_lm + ks * 32);
    __syncthreads();   // Q reads done; QP rows reused for P (warp-private)

    uint32_t p_lm = q_lm;

    // K/V tile loader: 64 rows x 8 chunks per matrix = 512 cp16 each; 2 per thread
    auto load_kv = [&](int it) {
        int stg = it % ATTN_STAGES;
        int kt = it * 64;
        #pragma unroll
        for (int j = 0; j < 2; j++) {
            int q = tid + j * 256;
            int r = q >> 3, c = q & 7;
            const __half* base = qkv + (size_t)(b * SEQ + kt + r) * 3 * D_MODEL + h * HD + c * 8;
            cp16(sbK + stg * KV_STAGE + r * AROW + c * 16, base + D_MODEL);
            cp16(sbV + stg * KV_STAGE + r * AROW + c * 16, base + 2 * D_MODEL);
        }
        cp_commit();
    };

    float o[8][4];
    #pragma unroll
    for (int nt = 0; nt < 8; nt++)
        #pragma unroll
        for (int j = 0; j < 4; j++) o[nt][j] = 0.0f;
    float ms0 = -3.0e38f, ms1 = -3.0e38f, ls0 = 0.0f, ls1 = 0.0f;

    int ntiles = (q0 + 128) >> 6;   // >= 2
    load_kv(0);
    load_kv(1);

    for (int it = 0; it < ntiles; it++) {
        cp_wait<1>();
        __syncthreads();
        if (it + 2 < ntiles) load_kv(it + 2);
        cp_commit();

        int kt = it * 64;
        // skip if this warp's rows are entirely above the key tile
        if (kt <= q0 + m0 + 15) {
            int stg = it % ATTN_STAGES;
            uint32_t k_lm = sbK + stg * KV_STAGE + (lane & 15) * AROW + ((lane >> 4) * 16);

            float sc[8][4];
            #pragma unroll
            for (int nt = 0; nt < 8; nt++)
                #pragma unroll
                for (int j = 0; j < 4; j++) sc[nt][j] = 0.0f;
            #pragma unroll
            for (int ks = 0; ks < 4; ks++) {
                uint32_t bf[8][2];
                #pragma unroll
                for (int p = 0; p < 4; p++)
                    ldsm_x4(bf[2*p][0], bf[2*p+1][0], bf[2*p][1], bf[2*p+1][1],
                            k_lm + p * 16 * AROW + ks * 32);
                #pragma unroll
                for (int nt = 0; nt < 8; nt++)
                    mma_f16(sc[nt], qa[ks], bf[nt]);
            }

            // causal mask (tile overlaps this warp's rows)
            if (kt + 63 > q0 + m0) {
                int r0 = q0 + m0 + gid, r1 = r0 + 8;
                #pragma unroll
                for (int nt = 0; nt < 8; nt++) {
                    int c0 = kt + nt * 8 + tig * 2;
                    if (c0     > r0) sc[nt][0] = -3.0e38f;
                    if (c0 + 1 > r0) sc[nt][1] = -3.0e38f;
                    if (c0     > r1) sc[nt][2] = -3.0e38f;
                    if (c0 + 1 > r1) sc[nt][3] = -3.0e38f;
                }
            }

            float tm0 = -3.0e38f, tm1 = -3.0e38f;
            #pragma unroll
            for (int nt = 0; nt < 8; nt++) {
                tm0 = fmaxf(tm0, fmaxf(sc[nt][0], sc[nt][1]));
                tm1 = fmaxf(tm1, fmaxf(sc[nt][2], sc[nt][3]));
            }
            #pragma unroll
            for (int off = 1; off <= 2; off <<= 1) {
                tm0 = fmaxf(tm0, __shfl_xor_sync(0xFFFFFFFFu, tm0, off));
                tm1 = fmaxf(tm1, __shfl_xor_sync(0xFFFFFFFFu, tm1, off));
            }
            float mn0 = fmaxf(ms0, tm0), mn1 = fmaxf(ms1, tm1);
            float cc0 = __expf(ms0 - mn0), cc1 = __expf(ms1 - mn1);
            ms0 = mn0; ms1 = mn1;
            float ps0 = 0.0f, ps1 = 0.0f;
            #pragma unroll
            for (int nt = 0; nt < 8; nt++) {
                sc[nt][0] = __expf(sc[nt][0] - mn0); ps0 += sc[nt][0];
                sc[nt][1] = __expf(sc[nt][1] - mn0); ps0 += sc[nt][1];
                sc[nt][2] = __expf(sc[nt][2] - mn1); ps1 += sc[nt][2];
                sc[nt][3] = __expf(sc[nt][3] - mn1); ps1 += sc[nt][3];
            }
            #pragma unroll
            for (int off = 1; off <= 2; off <<= 1) {
                ps0 += __shfl_xor_sync(0xFFFFFFFFu, ps0, off);
                ps1 += __shfl_xor_sync(0xFFFFFFFFu, ps1, off);
            }
            ls0 = ls0 * cc0 + ps0;
            ls1 = ls1 * cc1 + ps1;
            #pragma unroll
            for (int nt = 0; nt < 8; nt++) {
                o[nt][0] *= cc0; o[nt][1] *= cc0;
                o[nt][2] *= cc1; o[nt][3] *= cc1;
            }

            // P -> warp-private rows of QP
            __syncwarp();
            #pragma unroll
            for (int nt = 0; nt < 8; nt++) {
                int c0 = nt * 8 + tig * 2;
                __half2 p0 = __floats2half2_rn(sc[nt][0], sc[nt][1]);
                __half2 p1 = __floats2half2_rn(sc[nt][2], sc[nt][3]);
                *(__half2*)(QP + (m0 + gid    ) * AROW + c0 * 2) = p0;
                *(__half2*)(QP + (m0 + gid + 8) * AROW + c0 * 2) = p1;
            }
            __syncwarp();

            // O += P @ V
            #pragma unroll
            for (int ks = 0; ks < 4; ks++) {
                uint32_t pf[4];
                ldsm_x4(pf[0], pf[1], pf[2], pf[3], p_lm + ks * 32);
                uint32_t v_base = sbV + stg * KV_STAGE + (ks * 16 + (lane & 15)) * AROW
                                + ((lane >> 4) * 16);
                #pragma unroll
                for (int p = 0; p < 4; p++) {
                    uint32_t bf[2][2];
                    ldsm_x4_t(bf[0][0], bf[0][1], bf[1][0], bf[1][1], v_base + p * 32);
                    mma_f16(o[2*p    ], pf, bf[0]);
                    mma_f16(o[2*p + 1], pf, bf[1]);
                }
            }
        }
    }

    float inv0 = 1.0f / ls0, inv1 = 1.0f / ls1;
    int row0 = b * SEQ + q0 + m0 + gid;
    int row1 = row0 + 8;
    #pragma unroll
    for (int nt = 0; nt < 8; nt++) {
        int col = h * HD + nt * 8 + tig * 2;
        *(__half2*)(out + (size_t)row0 * D_MODEL + col) = __floats2half2_rn(o[nt][0] * inv0, o[nt][1] * inv0);
        *(__half2*)(out + (size_t)row1 * D_MODEL + col) = __floats2half2_rn(o[nt][2] * inv1, o[nt][3] * inv1);
    }
}

// ---------------- launch ----------------
extern "C" void kernel_launch(void* const* d_in, const int* in_sizes, int n_in,
                              void* d_out, int out_size)
{
    const float* x          = (const float*)d_in[0];
    const float* ln1_w      = (const float*)d_in[1];
    const float* ln1_b      = (const float*)d_in[2];
    const float* qkv_w      = (const float*)d_in[3];
    const float* qkv_b      = (const float*)d_in[4];
    const float* attn_out_w = (const float*)d_in[5];
    const float* attn_out_b = (const float*)d_in[6];
    const float* ln2_w      = (const float*)d_in[7];
    const float* ln2_b      = (const float*)d_in[8];
    const float* c_fc_w     = (const float*)d_in[9];
    const float* c_fc_b     = (const float*)d_in[10];
    const float* c_proj_w   = (const float*)d_in[11];
    const float* c_proj_b   = (const float*)d_in[12];
    float* out = (float*)d_out;

    float *XN, *H, *HN;
    __half *XNh, *QKVh, *Oh, *HNh, *Gh, *Wqkv, *Wproj, *Wfc, *Wpr2;
    cudaGetSymbolAddress((void**)&XN,   g_XN);
    cudaGetSymbolAddress((void**)&XNh,  g_XNh);
    cudaGetSymbolAddress((void**)&QKVh, g_QKVh);
    cudaGetSymbolAddress((void**)&Oh,   g_Oh);
    cudaGetSymbolAddress((void**)&H,    g_H);
    cudaGetSymbolAddress((void**)&HN,   g_HN);
    cudaGetSymbolAddress((void**)&HNh,  g_HNh);
    cudaGetSymbolAddress((void**)&Gh,   g_Gh);
    cudaGetSymbolAddress((void**)&Wqkv, g_Wqkv);
    cudaGetSymbolAddress((void**)&Wproj,g_Wproj);
    cudaGetSymbolAddress((void**)&Wfc,  g_Wfc);
    cudaGetSymbolAddress((void**)&Wpr2, g_Wpr2);

    cudaFuncSetAttribute(mma_gemm<EPI_BIAS_QKV>,  cudaFuncAttributeMaxDynamicSharedMemorySize, GEMM_SMEM_BYTES);
    cudaFuncSetAttribute(mma_gemm<EPI_BIAS_GELU>, cudaFuncAttributeMaxDynamicSharedMemorySize, GEMM_SMEM_BYTES);
    cudaFuncSetAttribute(mma_gemm<EPI_BIAS_RES>,  cudaFuncAttributeMaxDynamicSharedMemorySize, GEMM_SMEM_BYTES);
    cudaFuncSetAttribute(attn_kernel,             cudaFuncAttributeMaxDynamicSharedMemorySize, ATTN_SMEM);

    cvt_all_kernel<<<12288, 256>>>(qkv_w, attn_out_w, c_fc_w, c_proj_w,
                                   Wqkv, Wproj, Wfc, Wpr2);

    ln_kernel<<<ROWS / 8, 256>>>(x, ln1_w, ln1_b, XN, XNh);

    mma_gemm<EPI_BIAS_QKV><<<dim3(3 * D_MODEL / 128, ROWS / 128), 256, GEMM_SMEM_BYTES>>>(
        XNh, Wqkv, qkv_b, nullptr, QKVh, ROWS, 3 * D_MODEL, D_MODEL);

    attn_kernel<<<dim3(SEQ / 128, BATCH * NHEAD), 256, ATTN_SMEM>>>(QKVh, Oh);

    mma_gemm<EPI_BIAS_RES><<<dim3(D_MODEL / 128, ROWS / 128), 256, GEMM_SMEM_BYTES>>>(
        Oh, Wproj, attn_out_b, XN, H, ROWS, D_MODEL, D_MODEL);

    ln_kernel<<<ROWS / 8, 256>>>(H, ln2_w, ln2_b, HN, HNh);

    mma_gemm<EPI_BIAS_GELU><<<dim3(4 * D_MODEL / 128, ROWS / 128), 256, GEMM_SMEM_BYTES>>>(
        HNh, Wfc, c_fc_b, nullptr, Gh, ROWS, 4 * D_MODEL, D_MODEL);

    mma_gemm<EPI_BIAS_RES><<<dim3(D_MODEL / 128, ROWS / 128), 256, GEMM_SMEM_BYTES>>>(
        Gh, Wpr2, c_proj_b, HN, out, ROWS, D_MODEL, 4 * D_MODEL);
}

// round 15
// speedup vs baseline: 1.0577x; 1.0072x over previous
#include <cuda_runtime.h>
#include <cuda_fp16.h>
#include <math.h>
#include <stdint.h>

#define D_MODEL 1024
#define SEQ 2048
#define BATCH 2
#define NHEAD 16
#define HD 64
#define ROWS (BATCH*SEQ)   // 4096

// ---------------- scratch ----------------
__device__ float  g_XN [ROWS * D_MODEL];
__device__ __half g_XNh[ROWS * D_MODEL];
__device__ __half g_QKVh[ROWS * 3 * D_MODEL];   // fp16, Q pre-scaled by 0.125
__device__ __half g_Oh [ROWS * D_MODEL];
__device__ float  g_H  [ROWS * D_MODEL];
__device__ float  g_HN [ROWS * D_MODEL];
__device__ __half g_HNh[ROWS * D_MODEL];
__device__ __half g_Gh [ROWS * 4 * D_MODEL];
__device__ __half g_Wqkv [3 * D_MODEL * D_MODEL];
__device__ __half g_Wproj[D_MODEL * D_MODEL];
__device__ __half g_Wfc  [4 * D_MODEL * D_MODEL];
__device__ __half g_Wpr2 [D_MODEL * 4 * D_MODEL];

// ---------------- fused weight transpose (one launch) ----------------
__global__ __launch_bounds__(256) void cvt_all_kernel(const float* __restrict__ W0,
                                                      const float* __restrict__ W1,
                                                      const float* __restrict__ W2,
                                                      const float* __restrict__ W3,
                                                      __half* __restrict__ T0,
                                                      __half* __restrict__ T1,
                                                      __half* __restrict__ T2,
                                                      __half* __restrict__ T3)
{
    __shared__ float tile[32][33];
    int t = blockIdx.x;
    const float* W; __half* Wt; int K, N, local;
    if (t < 3072)      { W = W0; Wt = T0; K = 1024; N = 3072; local = t; }
    else if (t < 4096) { W = W1; Wt = T1; K = 1024; N = 1024; local = t - 3072; }
    else if (t < 8192) { W = W2; Wt = T2; K = 1024; N = 4096; local = t - 4096; }
    else               { W = W3; Wt = T3; K = 4096; N = 1024; local = t - 8192; }
    int nx = N >> 5;
    int n0 = (local % nx) * 32, k0 = (local / nx) * 32;
    int tx = threadIdx.x & 31, ty = threadIdx.x >> 5;
    #pragma unroll
    for (int j = 0; j < 4; j++) {
        int k = k0 + ty + j * 8;
        tile[ty + j * 8][tx] = W[(size_t)k * N + n0 + tx];
    }
    __syncthreads();
    #pragma unroll
    for (int j = 0; j < 4; j++) {
        int n = n0 + ty + j * 8;
        Wt[(size_t)n * K + k0 + tx] = __float2half(tile[tx][ty + j * 8]);
    }
}

// ---------------- LayerNorm: warp-per-row ----------------
__global__ __launch_bounds__(256) void ln_kernel(const float* __restrict__ x,
                                                 const float* __restrict__ w,
                                                 const float* __restrict__ b,
                                                 float* __restrict__ y,
                                                 __half* __restrict__ yh)
{
    int wid = threadIdx.x >> 5, lane = threadIdx.x & 31;
    int row = blockIdx.x * 8 + wid;
    const float4* xr = (const float4*)(x + (size_t)row * D_MODEL);
    float4 v[8];
    float s = 0.0f, sq = 0.0f;
    #pragma unroll
    for (int j = 0; j < 8; j++) {
        v[j] = xr[lane + j * 32];
        s  += v[j].x + v[j].y + v[j].z + v[j].w;
        sq += v[j].x*v[j].x + v[j].y*v[j].y + v[j].z*v[j].z + v[j].w*v[j].w;
    }
    #pragma unroll
    for (int o = 16; o > 0; o >>= 1) {
        s  += __shfl_xor_sync(0xFFFFFFFFu, s, o);
        sq += __shfl_xor_sync(0xFFFFFFFFu, sq, o);
    }
    float mu = s * (1.0f / D_MODEL);
    float rstd = rsqrtf(sq * (1.0f / D_MODEL) - mu * mu + 1e-5f);
    float4* yr = (float4*)(y + (size_t)row * D_MODEL);
    uint2* yhr = (uint2*)(yh + (size_t)row * D_MODEL);
    #pragma unroll
    for (int j = 0; j < 8; j++) {
        int idx = lane + j * 32;
        float4 wv = ((const float4*)w)[idx];
        float4 bv = ((const float4*)b)[idx];
        float4 r;
        r.x = (v[j].x - mu) * rstd * wv.x + bv.x;
        r.y = (v[j].y - mu) * rstd * wv.y + bv.y;
        r.z = (v[j].z - mu) * rstd * wv.z + bv.z;
        r.w = (v[j].w - mu) * rstd * wv.w + bv.w;
        yr[idx] = r;
        __half2 h0 = __floats2half2_rn(r.x, r.y);
        __half2 h1 = __floats2half2_rn(r.z, r.w);
        uint2 u = { *(uint32_t*)&h0, *(uint32_t*)&h1 };
        yhr[idx] = u;
    }
}

// ---------------- MMA helpers ----------------
__device__ __forceinline__ void mma_f16(float* d, const uint32_t* a, const uint32_t* b) {
    asm volatile(
        "mma.sync.aligned.m16n8k16.row.col.f32.f16.f16.f32 "
        "{%0,%1,%2,%3}, {%4,%5,%6,%7}, {%8,%9}, {%0,%1,%2,%3};\n"
        : "+f"(d[0]), "+f"(d[1]), "+f"(d[2]), "+f"(d[3])
        : "r"(a[0]), "r"(a[1]), "r"(a[2]), "r"(a[3]), "r"(b[0]), "r"(b[1]));
}
__device__ __forceinline__ void ldsm_x4(uint32_t& r0, uint32_t& r1, uint32_t& r2, uint32_t& r3,
                                        uint32_t addr) {
    asm volatile("ldmatrix.sync.aligned.m8n8.x4.shared.b16 {%0,%1,%2,%3}, [%4];"
                 : "=r"(r0), "=r"(r1), "=r"(r2), "=r"(r3) : "r"(addr));
}
__device__ __forceinline__ void ldsm_x4_t(uint32_t& r0, uint32_t& r1, uint32_t& r2, uint32_t& r3,
                                          uint32_t addr) {
    asm volatile("ldmatrix.sync.aligned.m8n8.x4.trans.shared.b16 {%0,%1,%2,%3}, [%4];"
                 : "=r"(r0), "=r"(r1), "=r"(r2), "=r"(r3) : "r"(addr));
}
__device__ __forceinline__ void cp16(uint32_t dst, const void* src) {
    asm volatile("cp.async.cg.shared.global [%0], [%1], 16;\n" :: "r"(dst), "l"(src));
}
__device__ __forceinline__ void cp_commit() {
    asm volatile("cp.async.commit_group;\n");
}
template <int N>
__device__ __forceinline__ void cp_wait() {
    asm volatile("cp.async.wait_group %0;\n" :: "n"(N));
}

// ---------------- fp16 GEMM (round-10 proven config) ----------------
#define EPI_BIAS      0
#define EPI_BIAS_GELU 1
#define EPI_BIAS_RES  2
#define EPI_BIAS_QKV  3

#define ROW_BYTES 144
#define STAGE_BYTES (128 * ROW_BYTES)
#define GEMM_STAGES 3
#define GEMM_SMEM_BYTES (GEMM_STAGES * 2 * STAGE_BYTES)   // 110592

template <int EPI>
__global__ __launch_bounds__(256, 2) void mma_gemm(const __half* __restrict__ A,
                                                   const __half* __restrict__ Bt,
                                                   const float* __restrict__ bias,
                                                   const float* __restrict__ res,
                                                   void* __restrict__ Cv,
                                                   int M, int N, int K)
{
    extern __shared__ uint8_t smem8[];
    uint32_t sbA = (uint32_t)__cvta_generic_to_shared(smem8);
    uint32_t sbB = sbA + GEMM_STAGES * STAGE_BYTES;

    int tid = threadIdx.x;
    int wid = tid >> 5, lane = tid & 31;
    int gid = lane >> 2, tig = lane & 3;
    int warp_m = wid & 1, warp_n = wid >> 1;
    int bx = blockIdx.x, by = blockIdx.y;

    const __half* Asrc[4];
    const __half* Bsrc[4];
    uint32_t Adst[4], Bdst[4];
    #pragma unroll
    for (int j = 0; j < 4; j++) {
        int q = tid + j * 256;
        int r = q >> 3, c = q & 7;
        Asrc[j] = A  + (size_t)(by * 128 + r) * K + c * 8;
        Bsrc[j] = Bt + (size_t)(bx * 128 + r) * K + c * 8;
        Adst[j] = sbA + r * ROW_BYTES + c * 16;
        Bdst[j] = sbB + r * ROW_BYTES + c * 16;
    }

    uint32_t a_lm = sbA + (warp_m * 64 + (lane & 15)) * ROW_BYTES + ((lane >> 4) * 16);
    uint32_t b_lm = sbB + (warp_n * 32 + (lane & 15)) * ROW_BYTES + ((lane >> 4) * 16);

    float acc[4][4][4];
    #pragma unroll
    for (int mt = 0; mt < 4; mt++)
        #pragma unroll
        for (int nt = 0; nt < 4; nt++)
            #pragma unroll
            for (int r = 0; r < 4; r++) acc[mt][nt][r] = 0.0f;

    int nIter = K >> 6;
    #pragma unroll
    for (int s = 0; s < 2; s++) {
        #pragma unroll
        for (int j = 0; j < 4; j++) {
            cp16(Adst[j] + s * STAGE_BYTES, Asrc[j] + s * 64);
            cp16(Bdst[j] + s * STAGE_BYTES, Bsrc[j] + s * 64);
        }
        cp_commit();
    }

    for (int it = 0; it < nIter; it++) {
        cp_wait<1>();
        __syncthreads();
        if (it + 2 < nIter) {
            int sb = (it + 2) % GEMM_STAGES;
            int k0 = (it + 2) << 6;
            #pragma unroll
            for (int j = 0; j < 4; j++) {
                cp16(Adst[j] + sb * STAGE_BYTES, Asrc[j] + k0);
                cp16(Bdst[j] + sb * STAGE_BYTES, Bsrc[j] + k0);
            }
        }
        cp_commit();

        int buf = it % GEMM_STAGES;
        uint32_t abase = a_lm + buf * STAGE_BYTES;
        uint32_t bbase = b_lm + buf * STAGE_BYTES;
        #pragma unroll
        for (int ks = 0; ks < 4; ks++) {
            uint32_t af[4][4], bf[4][2];
            #pragma unroll
            for (int mt = 0; mt < 4; mt++)
                ldsm_x4(af[mt][0], af[mt][1], af[mt][2], af[mt][3],
                        abase + mt * 16 * ROW_BYTES + ks * 32);
            #pragma unroll
            for (int p = 0; p < 2; p++)
                ldsm_x4(bf[2*p][0], bf[2*p+1][0], bf[2*p][1], bf[2*p+1][1],
                        bbase + p * 16 * ROW_BYTES + ks * 32);
            #pragma unroll
            for (int mt = 0; mt < 4; mt++)
                #pragma unroll
                for (int nt = 0; nt < 4; nt++)
                    mma_f16(acc[mt][nt], af[mt], bf[nt]);
        }
    }

    #pragma unroll
    for (int mt = 0; mt < 4; mt++) {
        #pragma unroll
        for (int nt = 0; nt < 4; nt++) {
            int row0 = by * 128 + warp_m * 64 + mt * 16 + gid;
            int col  = bx * 128 + warp_n * 32 + nt * 8 + tig * 2;
            float b0 = bias[col], b1 = bias[col + 1];
            #pragma unroll
            for (int half_i = 0; half_i < 2; half_i++) {
                int row = row0 + half_i * 8;
                float v0 = acc[mt][nt][half_i * 2 + 0] + b0;
                float v1 = acc[mt][nt][half_i * 2 + 1] + b1;
                if (EPI == EPI_BIAS_QKV) {
                    if (col < D_MODEL) { v0 *= 0.125f; v1 *= 0.125f; }
                    __half2 hv = __floats2half2_rn(v0, v1);
                    *(__half2*)((__half*)Cv + (size_t)row * N + col) = hv;
                } else if (EPI == EPI_BIAS_GELU) {
                    v0 = 0.5f * v0 * (1.0f + erff(v0 * 0.70710678118654752f));
                    v1 = 0.5f * v1 * (1.0f + erff(v1 * 0.70710678118654752f));
                    __half2 hv = __floats2half2_rn(v0, v1);
                    *(__half2*)((__half*)Cv + (size_t)row * N + col) = hv;
                } else {
                    if (EPI == EPI_BIAS_RES) {
                        float2 rv = *(const float2*)(res + (size_t)row * N + col);
                        v0 += rv.x; v1 += rv.y;
                    }
                    float2 o2 = { v0, v1 };
                    *(float2*)((float*)Cv + (size_t)row * N + col) = o2;
                }
            }
        }
    }
}

// ---------------- Flash attention: heavy-first order, 4-stage cp.async ----------------
#define AROW 144
#define KV_STAGE (64 * AROW)                    // 9216 per matrix per stage
#define ATTN_STAGES 4
#define ATTN_SMEM (128 * AROW + 2 * ATTN_STAGES * KV_STAGE)   // 18432 + 73728 = 92160

__global__ __launch_bounds__(256, 2) void attn_kernel(const __half* __restrict__ qkv,
                                                      __half* __restrict__ out)
{
    extern __shared__ uint8_t smem8[];
    uint32_t sb = (uint32_t)__cvta_generic_to_shared(smem8);
    uint8_t* QP = smem8;
    uint32_t sbQP = sb;
    uint32_t sbK = sb + 128 * AROW;
    uint32_t sbV = sbK + ATTN_STAGES * KV_STAGE;

    int bh = blockIdx.y;
    int b = bh >> 4, h = bh & 15;
    // heavy-first: largest q0 launches first (LPT scheduling for the causal triangle)
    int q0 = (gridDim.x - 1 - blockIdx.x) * 128;
    int tid = threadIdx.x;
    int wid = tid >> 5, lane = tid & 31;
    int gid = lane >> 2, tig = lane & 3;
    int m0 = wid * 16;

    for (int i = tid; i < 128 * 8; i += 256) {
        int r = i >> 3, c = i & 7;
        *(uint4*)(QP + r * AROW + c * 16) =
            *(const uint4*)(qkv + (size_t)(b * SEQ + q0 + r) * 3 * D_MODEL + h * HD + c * 8);
    }
    __syncthreads();

    uint32_t q_lm = sbQP + (m0 + (lane & 15)) * AROW + ((lane >> 4) * 16);
    uint32_t qa[4][4];
    #pragma unroll
    for (int ks = 0; ks < 4; ks++)
        ldsm_x4(qa[ks][0], qa[ks][1], qa[ks][2], qa[ks][3], q_lm + ks * 32);
    __syncthreads();

    uint32_t p_lm = q_lm;

    auto load_kv = [&](int it) {
        int stg = it % ATTN_STAGES;
        int kt = it * 64;
        #pragma unroll
        for (int j = 0; j < 2; j++) {
            int q = tid + j * 256;
            int r = q >> 3, c = q & 7;
            const __half* base = qkv + (size_t)(b * SEQ + kt + r) * 3 * D_MODEL + h * HD + c * 8;
            cp16(sbK + stg * KV_STAGE + r * AROW + c * 16, base + D_MODEL);
            cp16(sbV + stg * KV_STAGE + r * AROW + c * 16, base + 2 * D_MODEL);
        }
        cp_commit();
    };

    float o[8][4];
    #pragma unroll
    for (int nt = 0; nt < 8; nt++)
        #pragma unroll
        for (int j = 0; j < 4; j++) o[nt][j] = 0.0f;
    float ms0 = -3.0e38f, ms1 = -3.0e38f, ls0 = 0.0f, ls1 = 0.0f;

    int ntiles = (q0 + 128) >> 6;   // >= 2
    load_kv(0);
    load_kv(1);
    if (ntiles > 2) load_kv(2);

    for (int it = 0; it < ntiles; it++) {
        cp_wait<2>();
        __syncthreads();
        if (it + 3 < ntiles) load_kv(it + 3);
        cp_commit();

        int kt = it * 64;
        if (kt <= q0 + m0 + 15) {
            int stg = it % ATTN_STAGES;
            uint32_t k_lm = sbK + stg * KV_STAGE + (lane & 15) * AROW + ((lane >> 4) * 16);

            float sc[8][4];
            #pragma unroll
            for (int nt = 0; nt < 8; nt++)
                #pragma unroll
                for (int j = 0; j < 4; j++) sc[nt][j] = 0.0f;
            #pragma unroll
            for (int ks = 0; ks < 4; ks++) {
                uint32_t bf[8][2];
                #pragma unroll
                for (int p = 0; p < 4; p++)
                    ldsm_x4(bf[2*p][0], bf[2*p+1][0], bf[2*p][1], bf[2*p+1][1],
                            k_lm + p * 16 * AROW + ks * 32);
                #pragma unroll
                for (int nt = 0; nt < 8; nt++)
                    mma_f16(sc[nt], qa[ks], bf[nt]);
            }

            if (kt + 63 > q0 + m0) {
                int r0 = q0 + m0 + gid, r1 = r0 + 8;
                #pragma unroll
                for (int nt = 0; nt < 8; nt++) {
                    int c0 = kt + nt * 8 + tig * 2;
                    if (c0     > r0) sc[nt][0] = -3.0e38f;
                    if (c0 + 1 > r0) sc[nt][1] = -3.0e38f;
                    if (c0     > r1) sc[nt][2] = -3.0e38f;
                    if (c0 + 1 > r1) sc[nt][3] = -3.0e38f;
                }
            }

            float tm0 = -3.0e38f, tm1 = -3.0e38f;
            #pragma unroll
            for (int nt = 0; nt < 8; nt++) {
                tm0 = fmaxf(tm0, fmaxf(sc[nt][0], sc[nt][1]));
                tm1 = fmaxf(tm1, fmaxf(sc[nt][2], sc[nt][3]));
            }
            #pragma unroll
            for (int off = 1; off <= 2; off <<= 1) {
                tm0 = fmaxf(tm0, __shfl_xor_sync(0xFFFFFFFFu, tm0, off));
                tm1 = fmaxf(tm1, __shfl_xor_sync(0xFFFFFFFFu, tm1, off));
            }
            float mn0 = fmaxf(ms0, tm0), mn1 = fmaxf(ms1, tm1);
            float cc0 = __expf(ms0 - mn0), cc1 = __expf(ms1 - mn1);
            ms0 = mn0; ms1 = mn1;
            float ps0 = 0.0f, ps1 = 0.0f;
            #pragma unroll
            for (int nt = 0; nt < 8; nt++) {
                sc[nt][0] = __expf(sc[nt][0] - mn0); ps0 += sc[nt][0];
                sc[nt][1] = __expf(sc[nt][1] - mn0); ps0 += sc[nt][1];
                sc[nt][2] = __expf(sc[nt][2] - mn1); ps1 += sc[nt][2];
                sc[nt][3] = __expf(sc[nt][3] - mn1); ps1 += sc[nt][3];
            }
            #pragma unroll
            for (int off = 1; off <= 2; off <<= 1) {
                ps0 += __shfl_xor_sync(0xFFFFFFFFu, ps0, off);
                ps1 += __shfl_xor_sync(0xFFFFFFFFu, ps1, off);
            }
            ls0 = ls0 * cc0 + ps0;
            ls1 = ls1 * cc1 + ps1;
            #pragma unroll
            for (int nt = 0; nt < 8; nt++) {
                o[nt][0] *= cc0; o[nt][1] *= cc0;
                o[nt][2] *= cc1; o[nt][3] *= cc1;
            }

            __syncwarp();
            #pragma unroll
            for (int nt = 0; nt < 8; nt++) {
                int c0 = nt * 8 + tig * 2;
                __half2 p0 = __floats2half2_rn(sc[nt][0], sc[nt][1]);
                __half2 p1 = __floats2half2_rn(sc[nt][2], sc[nt][3]);
                *(__half2*)(QP + (m0 + gid    ) * AROW + c0 * 2) = p0;
                *(__half2*)(QP + (m0 + gid + 8) * AROW + c0 * 2) = p1;
            }
            __syncwarp();

            #pragma unroll
            for (int ks = 0; ks < 4; ks++) {
                uint32_t pf[4];
                ldsm_x4(pf[0], pf[1], pf[2], pf[3], p_lm + ks * 32);
                uint32_t v_base = sbV + stg * KV_STAGE + (ks * 16 + (lane & 15)) * AROW
                                + ((lane >> 4) * 16);
                #pragma unroll
                for (int p = 0; p < 4; p++) {
                    uint32_t bf[2][2];
                    ldsm_x4_t(bf[0][0], bf[0][1], bf[1][0], bf[1][1], v_base + p * 32);
                    mma_f16(o[2*p    ], pf, bf[0]);
                    mma_f16(o[2*p + 1], pf, bf[1]);
                }
            }
        }
    }

    float inv0 = 1.0f / ls0, inv1 = 1.0f / ls1;
    int row0 = b * SEQ + q0 + m0 + gid;
    int row1 = row0 + 8;
    #pragma unroll
    for (int nt = 0; nt < 8; nt++) {
        int col = h * HD + nt * 8 + tig * 2;
        *(__half2*)(out + (size_t)row0 * D_MODEL + col) = __floats2half2_rn(o[nt][0] * inv0, o[nt][1] * inv0);
        *(__half2*)(out + (size_t)row1 * D_MODEL + col) = __floats2half2_rn(o[nt][2] * inv1, o[nt][3] * inv1);
    }
}

// ---------------- launch ----------------
extern "C" void kernel_launch(void* const* d_in, const int* in_sizes, int n_in,
                              void* d_out, int out_size)
{
    const float* x          = (const float*)d_in[0];
    const float* ln1_w      = (const float*)d_in[1];
    const float* ln1_b      = (const float*)d_in[2];
    const float* qkv_w      = (const float*)d_in[3];
    const float* qkv_b      = (const float*)d_in[4];
    const float* attn_out_w = (const float*)d_in[5];
    const float* attn_out_b = (const float*)d_in[6];
    const float* ln2_w      = (const float*)d_in[7];
    const float* ln2_b      = (const float*)d_in[8];
    const float* c_fc_w     = (const float*)d_in[9];
    const float* c_fc_b     = (const float*)d_in[10];
    const float* c_proj_w   = (const float*)d_in[11];
    const float* c_proj_b   = (const float*)d_in[12];
    float* out = (float*)d_out;

    float *XN, *H, *HN;
    __half *XNh, *QKVh, *Oh, *HNh, *Gh, *Wqkv, *Wproj, *Wfc, *Wpr2;
    cudaGetSymbolAddress((void**)&XN,   g_XN);
    cudaGetSymbolAddress((void**)&XNh,  g_XNh);
    cudaGetSymbolAddress((void**)&QKVh, g_QKVh);
    cudaGetSymbolAddress((void**)&Oh,   g_Oh);
    cudaGetSymbolAddress((void**)&H,    g_H);
    cudaGetSymbolAddress((void**)&HN,   g_HN);
    cudaGetSymbolAddress((void**)&HNh,  g_HNh);
    cudaGetSymbolAddress((void**)&Gh,   g_Gh);
    cudaGetSymbolAddress((void**)&Wqkv, g_Wqkv);
    cudaGetSymbolAddress((void**)&Wproj,g_Wproj);
    cudaGetSymbolAddress((void**)&Wfc,  g_Wfc);
    cudaGetSymbolAddress((void**)&Wpr2, g_Wpr2);

    cudaFuncSetAttribute(mma_gemm<EPI_BIAS_QKV>,  cudaFuncAttributeMaxDynamicSharedMemorySize, GEMM_SMEM_BYTES);
    cudaFuncSetAttribute(mma_gemm<EPI_BIAS_GELU>, cudaFuncAttributeMaxDynamicSharedMemorySize, GEMM_SMEM_BYTES);
    cudaFuncSetAttribute(mma_gemm<EPI_BIAS_RES>,  cudaFuncAttributeMaxDynamicSharedMemorySize, GEMM_SMEM_BYTES);
    cudaFuncSetAttribute(attn_kernel,             cudaFuncAttributeMaxDynamicSharedMemorySize, ATTN_SMEM);

    cvt_all_kernel<<<12288, 256>>>(qkv_w, attn_out_w, c_fc_w, c_proj_w,
                                   Wqkv, Wproj, Wfc, Wpr2);

    ln_kernel<<<ROWS / 8, 256>>>(x, ln1_w, ln1_b, XN, XNh);

    mma_gemm<EPI_BIAS_QKV><<<dim3(3 * D_MODEL / 128, ROWS / 128), 256, GEMM_SMEM_BYTES>>>(
        XNh, Wqkv, qkv_b, nullptr, QKVh, ROWS, 3 * D_MODEL, D_MODEL);

    attn_kernel<<<dim3(SEQ / 128, BATCH * NHEAD), 256, ATTN_SMEM>>>(QKVh, Oh);

    mma_gemm<EPI_BIAS_RES><<<dim3(D_MODEL / 128, ROWS / 128), 256, GEMM_SMEM_BYTES>>>(
        Oh, Wproj, attn_out_b, XN, H, ROWS, D_MODEL, D_MODEL);

    ln_kernel<<<ROWS / 8, 256>>>(H, ln2_w, ln2_b, HN, HNh);

    mma_gemm<EPI_BIAS_GELU><<<dim3(4 * D_MODEL / 128, ROWS / 128), 256, GEMM_SMEM_BYTES>>>(
        HNh, Wfc, c_fc_b, nullptr, Gh, ROWS, 4 * D_MODEL, D_MODEL);

    mma_gemm<EPI_BIAS_RES><<<dim3(D_MODEL / 128, ROWS / 128), 256, GEMM_SMEM_BYTES>>>(
        Gh, Wpr2, c_proj_b, HN, out, ROWS, D_MODEL, 4 * D_MODEL);
}

// round 16
// speedup vs baseline: 1.0610x; 1.0031x over previous
#include <cuda_runtime.h>
#include <cuda_fp16.h>
#include <math.h>
#include <stdint.h>

#define D_MODEL 1024
#define SEQ 2048
#define BATCH 2
#define NHEAD 16
#define HD 64
#define ROWS (BATCH*SEQ)   // 4096

// ---------------- scratch ----------------
__device__ float  g_XN [ROWS * D_MODEL];
__device__ __half g_XNh[ROWS * D_MODEL];
__device__ __half g_QKVh[ROWS * 3 * D_MODEL];   // fp16, Q pre-scaled by 0.125
__device__ __half g_Oh [ROWS * D_MODEL];
__device__ float  g_H  [ROWS * D_MODEL];
__device__ float  g_HN [ROWS * D_MODEL];
__device__ __half g_HNh[ROWS * D_MODEL];
__device__ __half g_Gh [ROWS * 4 * D_MODEL];
__device__ __half g_Wqkv [3 * D_MODEL * D_MODEL];
__device__ __half g_Wproj[D_MODEL * D_MODEL];
__device__ __half g_Wfc  [4 * D_MODEL * D_MODEL];
__device__ __half g_Wpr2 [D_MODEL * 4 * D_MODEL];

// ---------------- fused weight transpose (one launch) ----------------
__global__ __launch_bounds__(256) void cvt_all_kernel(const float* __restrict__ W0,
                                                      const float* __restrict__ W1,
                                                      const float* __restrict__ W2,
                                                      const float* __restrict__ W3,
                                                      __half* __restrict__ T0,
                                                      __half* __restrict__ T1,
                                                      __half* __restrict__ T2,
                                                      __half* __restrict__ T3)
{
    __shared__ float tile[32][33];
    int t = blockIdx.x;
    const float* W; __half* Wt; int K, N, local;
    if (t < 3072)      { W = W0; Wt = T0; K = 1024; N = 3072; local = t; }
    else if (t < 4096) { W = W1; Wt = T1; K = 1024; N = 1024; local = t - 3072; }
    else if (t < 8192) { W = W2; Wt = T2; K = 1024; N = 4096; local = t - 4096; }
    else               { W = W3; Wt = T3; K = 4096; N = 1024; local = t - 8192; }
    int nx = N >> 5;
    int n0 = (local % nx) * 32, k0 = (local / nx) * 32;
    int tx = threadIdx.x & 31, ty = threadIdx.x >> 5;
    #pragma unroll
    for (int j = 0; j < 4; j++) {
        int k = k0 + ty + j * 8;
        tile[ty + j * 8][tx] = W[(size_t)k * N + n0 + tx];
    }
    __syncthreads();
    #pragma unroll
    for (int j = 0; j < 4; j++) {
        int n = n0 + ty + j * 8;
        Wt[(size_t)n * K + k0 + tx] = __float2half(tile[tx][ty + j * 8]);
    }
}

// ---------------- LayerNorm: warp-per-row ----------------
__global__ __launch_bounds__(256) void ln_kernel(const float* __restrict__ x,
                                                 const float* __restrict__ w,
                                                 const float* __restrict__ b,
                                                 float* __restrict__ y,
                                                 __half* __restrict__ yh)
{
    int wid = threadIdx.x >> 5, lane = threadIdx.x & 31;
    int row = blockIdx.x * 8 + wid;
    const float4* xr = (const float4*)(x + (size_t)row * D_MODEL);
    float4 v[8];
    float s = 0.0f, sq = 0.0f;
    #pragma unroll
    for (int j = 0; j < 8; j++) {
        v[j] = xr[lane + j * 32];
        s  += v[j].x + v[j].y + v[j].z + v[j].w;
        sq += v[j].x*v[j].x + v[j].y*v[j].y + v[j].z*v[j].z + v[j].w*v[j].w;
    }
    #pragma unroll
    for (int o = 16; o > 0; o >>= 1) {
        s  += __shfl_xor_sync(0xFFFFFFFFu, s, o);
        sq += __shfl_xor_sync(0xFFFFFFFFu, sq, o);
    }
    float mu = s * (1.0f / D_MODEL);
    float rstd = rsqrtf(sq * (1.0f / D_MODEL) - mu * mu + 1e-5f);
    float4* yr = (float4*)(y + (size_t)row * D_MODEL);
    uint2* yhr = (uint2*)(yh + (size_t)row * D_MODEL);
    #pragma unroll
    for (int j = 0; j < 8; j++) {
        int idx = lane + j * 32;
        float4 wv = ((const float4*)w)[idx];
        float4 bv = ((const float4*)b)[idx];
        float4 r;
        r.x = (v[j].x - mu) * rstd * wv.x + bv.x;
        r.y = (v[j].y - mu) * rstd * wv.y + bv.y;
        r.z = (v[j].z - mu) * rstd * wv.z + bv.z;
        r.w = (v[j].w - mu) * rstd * wv.w + bv.w;
        yr[idx] = r;
        __half2 h0 = __floats2half2_rn(r.x, r.y);
        __half2 h1 = __floats2half2_rn(r.z, r.w);
        uint2 u = { *(uint32_t*)&h0, *(uint32_t*)&h1 };
        yhr[idx] = u;
    }
}

// ---------------- MMA helpers ----------------
__device__ __forceinline__ void mma_f16(float* d, const uint32_t* a, const uint32_t* b) {
    asm volatile(
        "mma.sync.aligned.m16n8k16.row.col.f32.f16.f16.f32 "
        "{%0,%1,%2,%3}, {%4,%5,%6,%7}, {%8,%9}, {%0,%1,%2,%3};\n"
        : "+f"(d[0]), "+f"(d[1]), "+f"(d[2]), "+f"(d[3])
        : "r"(a[0]), "r"(a[1]), "r"(a[2]), "r"(a[3]), "r"(b[0]), "r"(b[1]));
}
__device__ __forceinline__ void ldsm_x4(uint32_t& r0, uint32_t& r1, uint32_t& r2, uint32_t& r3,
                                        uint32_t addr) {
    asm volatile("ldmatrix.sync.aligned.m8n8.x4.shared.b16 {%0,%1,%2,%3}, [%4];"
                 : "=r"(r0), "=r"(r1), "=r"(r2), "=r"(r3) : "r"(addr));
}
__device__ __forceinline__ void ldsm_x4_t(uint32_t& r0, uint32_t& r1, uint32_t& r2, uint32_t& r3,
                                          uint32_t addr) {
    asm volatile("ldmatrix.sync.aligned.m8n8.x4.trans.shared.b16 {%0,%1,%2,%3}, [%4];"
                 : "=r"(r0), "=r"(r1), "=r"(r2), "=r"(r3) : "r"(addr));
}
__device__ __forceinline__ void cp16(uint32_t dst, const void* src) {
    asm volatile("cp.async.cg.shared.global [%0], [%1], 16;\n" :: "r"(dst), "l"(src));
}
__device__ __forceinline__ void cp_commit() {
    asm volatile("cp.async.commit_group;\n");
}
template <int N>
__device__ __forceinline__ void cp_wait() {
    asm volatile("cp.async.wait_group %0;\n" :: "n"(N));
}

// ---------------- fp16 GEMM (round-10 proven config) ----------------
#define EPI_BIAS      0
#define EPI_BIAS_GELU 1
#define EPI_BIAS_RES  2
#define EPI_BIAS_QKV  3

#define ROW_BYTES 144
#define STAGE_BYTES (128 * ROW_BYTES)
#define GEMM_STAGES 3
#define GEMM_SMEM_BYTES (GEMM_STAGES * 2 * STAGE_BYTES)   // 110592

template <int EPI>
__global__ __launch_bounds__(256, 2) void mma_gemm(const __half* __restrict__ A,
                                                   const __half* __restrict__ Bt,
                                                   const float* __restrict__ bias,
                                                   const float* __restrict__ res,
                                                   void* __restrict__ Cv,
                                                   int M, int N, int K)
{
    extern __shared__ uint8_t smem8[];
    uint32_t sbA = (uint32_t)__cvta_generic_to_shared(smem8);
    uint32_t sbB = sbA + GEMM_STAGES * STAGE_BYTES;

    int tid = threadIdx.x;
    int wid = tid >> 5, lane = tid & 31;
    int gid = lane >> 2, tig = lane & 3;
    int warp_m = wid & 1, warp_n = wid >> 1;
    int bx = blockIdx.x, by = blockIdx.y;

    const __half* Asrc[4];
    const __half* Bsrc[4];
    uint32_t Adst[4], Bdst[4];
    #pragma unroll
    for (int j = 0; j < 4; j++) {
        int q = tid + j * 256;
        int r = q >> 3, c = q & 7;
        Asrc[j] = A  + (size_t)(by * 128 + r) * K + c * 8;
        Bsrc[j] = Bt + (size_t)(bx * 128 + r) * K + c * 8;
        Adst[j] = sbA + r * ROW_BYTES + c * 16;
        Bdst[j] = sbB + r * ROW_BYTES + c * 16;
    }

    uint32_t a_lm = sbA + (warp_m * 64 + (lane & 15)) * ROW_BYTES + ((lane >> 4) * 16);
    uint32_t b_lm = sbB + (warp_n * 32 + (lane & 15)) * ROW_BYTES + ((lane >> 4) * 16);

    float acc[4][4][4];
    #pragma unroll
    for (int mt = 0; mt < 4; mt++)
        #pragma unroll
        for (int nt = 0; nt < 4; nt++)
            #pragma unroll
            for (int r = 0; r < 4; r++) acc[mt][nt][r] = 0.0f;

    int nIter = K >> 6;
    #pragma unroll
    for (int s = 0; s < 2; s++) {
        #pragma unroll
        for (int j = 0; j < 4; j++) {
            cp16(Adst[j] + s * STAGE_BYTES, Asrc[j] + s * 64);
            cp16(Bdst[j] + s * STAGE_BYTES, Bsrc[j] + s * 64);
        }
        cp_commit();
    }

    for (int it = 0; it < nIter; it++) {
        cp_wait<1>();
        __syncthreads();
        if (it + 2 < nIter) {
            int sb = (it + 2) % GEMM_STAGES;
            int k0 = (it + 2) << 6;
            #pragma unroll
            for (int j = 0; j < 4; j++) {
                cp16(Adst[j] + sb * STAGE_BYTES, Asrc[j] + k0);
                cp16(Bdst[j] + sb * STAGE_BYTES, Bsrc[j] + k0);
            }
        }
        cp_commit();

        int buf = it % GEMM_STAGES;
        uint32_t abase = a_lm + buf * STAGE_BYTES;
        uint32_t bbase = b_lm + buf * STAGE_BYTES;
        #pragma unroll
        for (int ks = 0; ks < 4; ks++) {
            uint32_t af[4][4], bf[4][2];
            #pragma unroll
            for (int mt = 0; mt < 4; mt++)
                ldsm_x4(af[mt][0], af[mt][1], af[mt][2], af[mt][3],
                        abase + mt * 16 * ROW_BYTES + ks * 32);
            #pragma unroll
            for (int p = 0; p < 2; p++)
                ldsm_x4(bf[2*p][0], bf[2*p+1][0], bf[2*p][1], bf[2*p+1][1],
                        bbase + p * 16 * ROW_BYTES + ks * 32);
            #pragma unroll
            for (int mt = 0; mt < 4; mt++)
                #pragma unroll
                for (int nt = 0; nt < 4; nt++)
                    mma_f16(acc[mt][nt], af[mt], bf[nt]);
        }
    }

    #pragma unroll
    for (int mt = 0; mt < 4; mt++) {
        #pragma unroll
        for (int nt = 0; nt < 4; nt++) {
            int row0 = by * 128 + warp_m * 64 + mt * 16 + gid;
            int col  = bx * 128 + warp_n * 32 + nt * 8 + tig * 2;
            float b0 = bias[col], b1 = bias[col + 1];
            #pragma unroll
            for (int half_i = 0; half_i < 2; half_i++) {
                int row = row0 + half_i * 8;
                float v0 = acc[mt][nt][half_i * 2 + 0] + b0;
                float v1 = acc[mt][nt][half_i * 2 + 1] + b1;
                if (EPI == EPI_BIAS_QKV) {
                    if (col < D_MODEL) { v0 *= 0.125f; v1 *= 0.125f; }
                    __half2 hv = __floats2half2_rn(v0, v1);
                    *(__half2*)((__half*)Cv + (size_t)row * N + col) = hv;
                } else if (EPI == EPI_BIAS_GELU) {
                    v0 = 0.5f * v0 * (1.0f + erff(v0 * 0.70710678118654752f));
                    v1 = 0.5f * v1 * (1.0f + erff(v1 * 0.70710678118654752f));
                    __half2 hv = __floats2half2_rn(v0, v1);
                    *(__half2*)((__half*)Cv + (size_t)row * N + col) = hv;
                } else {
                    if (EPI == EPI_BIAS_RES) {
                        float2 rv = *(const float2*)(res + (size_t)row * N + col);
                        v0 += rv.x; v1 += rv.y;
                    }
                    float2 o2 = { v0, v1 };
                    *(float2*)((float*)Cv + (size_t)row * N + col) = o2;
                }
            }
        }
    }
}

// ---------------- Flash attention: heavy-first, 4-stage cp.async (race-fixed) ----------------
#define AROW 144
#define KV_STAGE (64 * AROW)
#define ATTN_STAGES 4
#define ATTN_SMEM (128 * AROW + 2 * ATTN_STAGES * KV_STAGE)   // 92160

__global__ __launch_bounds__(256, 2) void attn_kernel(const __half* __restrict__ qkv,
                                                      __half* __restrict__ out)
{
    extern __shared__ uint8_t smem8[];
    uint32_t sb = (uint32_t)__cvta_generic_to_shared(smem8);
    uint8_t* QP = smem8;
    uint32_t sbQP = sb;
    uint32_t sbK = sb + 128 * AROW;
    uint32_t sbV = sbK + ATTN_STAGES * KV_STAGE;

    int bh = blockIdx.y;
    int b = bh >> 4, h = bh & 15;
    int q0 = (gridDim.x - 1 - blockIdx.x) * 128;   // heavy-first
    int tid = threadIdx.x;
    int wid = tid >> 5, lane = tid & 31;
    int gid = lane >> 2, tig = lane & 3;
    int m0 = wid * 16;

    for (int i = tid; i < 128 * 8; i += 256) {
        int r = i >> 3, c = i & 7;
        *(uint4*)(QP + r * AROW + c * 16) =
            *(const uint4*)(qkv + (size_t)(b * SEQ + q0 + r) * 3 * D_MODEL + h * HD + c * 8);
    }
    __syncthreads();

    uint32_t q_lm = sbQP + (m0 + (lane & 15)) * AROW + ((lane >> 4) * 16);
    uint32_t qa[4][4];
    #pragma unroll
    for (int ks = 0; ks < 4; ks++)
        ldsm_x4(qa[ks][0], qa[ks][1], qa[ks][2], qa[ks][3], q_lm + ks * 32);
    __syncthreads();

    uint32_t p_lm = q_lm;

    auto load_kv = [&](int it) {
        int stg = it % ATTN_STAGES;
        int kt = it * 64;
        #pragma unroll
        for (int j = 0; j < 2; j++) {
            int q = tid + j * 256;
            int r = q >> 3, c = q & 7;
            const __half* base = qkv + (size_t)(b * SEQ + kt + r) * 3 * D_MODEL + h * HD + c * 8;
            cp16(sbK + stg * KV_STAGE + r * AROW + c * 16, base + D_MODEL);
            cp16(sbV + stg * KV_STAGE + r * AROW + c * 16, base + 2 * D_MODEL);
        }
        cp_commit();
    };

    float o[8][4];
    #pragma unroll
    for (int nt = 0; nt < 8; nt++)
        #pragma unroll
        for (int j = 0; j < 4; j++) o[nt][j] = 0.0f;
    float ms0 = -3.0e38f, ms1 = -3.0e38f, ls0 = 0.0f, ls1 = 0.0f;

    int ntiles = (q0 + 128) >> 6;   // >= 2
    // prologue: ALWAYS exactly 3 commit groups, so cp_wait<2> at it=0 drains group 0
    load_kv(0);
    load_kv(1);
    if (ntiles > 2) load_kv(2); else cp_commit();   // empty group keeps the ledger aligned

    for (int it = 0; it < ntiles; it++) {
        cp_wait<2>();
        __syncthreads();
        if (it + 3 < ntiles) load_kv(it + 3);
        else cp_commit();    // one commit per iteration, always

        int kt = it * 64;
        if (kt <= q0 + m0 + 15) {
            int stg = it % ATTN_STAGES;
            uint32_t k_lm = sbK + stg * KV_STAGE + (lane & 15) * AROW + ((lane >> 4) * 16);

            float sc[8][4];
            #pragma unroll
            for (int nt = 0; nt < 8; nt++)
                #pragma unroll
                for (int j = 0; j < 4; j++) sc[nt][j] = 0.0f;
            #pragma unroll
            for (int ks = 0; ks < 4; ks++) {
                uint32_t bf[8][2];
                #pragma unroll
                for (int p = 0; p < 4; p++)
                    ldsm_x4(bf[2*p][0], bf[2*p+1][0], bf[2*p][1], bf[2*p+1][1],
                            k_lm + p * 16 * AROW + ks * 32);
                #pragma unroll
                for (int nt = 0; nt < 8; nt++)
                    mma_f16(sc[nt], qa[ks], bf[nt]);
            }

            if (kt + 63 > q0 + m0) {
                int r0 = q0 + m0 + gid, r1 = r0 + 8;
                #pragma unroll
                for (int nt = 0; nt < 8; nt++) {
                    int c0 = kt + nt * 8 + tig * 2;
                    if (c0     > r0) sc[nt][0] = -3.0e38f;
                    if (c0 + 1 > r0) sc[nt][1] = -3.0e38f;
                    if (c0     > r1) sc[nt][2] = -3.0e38f;
                    if (c0 + 1 > r1) sc[nt][3] = -3.0e38f;
                }
            }

            float tm0 = -3.0e38f, tm1 = -3.0e38f;
            #pragma unroll
            for (int nt = 0; nt < 8; nt++) {
                tm0 = fmaxf(tm0, fmaxf(sc[nt][0], sc[nt][1]));
                tm1 = fmaxf(tm1, fmaxf(sc[nt][2], sc[nt][3]));
            }
            #pragma unroll
            for (int off = 1; off <= 2; off <<= 1) {
                tm0 = fmaxf(tm0, __shfl_xor_sync(0xFFFFFFFFu, tm0, off));
                tm1 = fmaxf(tm1, __shfl_xor_sync(0xFFFFFFFFu, tm1, off));
            }
            float mn0 = fmaxf(ms0, tm0), mn1 = fmaxf(ms1, tm1);
            float cc0 = __expf(ms0 - mn0), cc1 = __expf(ms1 - mn1);
            ms0 = mn0; ms1 = mn1;
            float ps0 = 0.0f, ps1 = 0.0f;
            #pragma unroll
            for (int nt = 0; nt < 8; nt++) {
                sc[nt][0] = __expf(sc[nt][0] - mn0); ps0 += sc[nt][0];
                sc[nt][1] = __expf(sc[nt][1] - mn0); ps0 += sc[nt][1];
                sc[nt][2] = __expf(sc[nt][2] - mn1); ps1 += sc[nt][2];
                sc[nt][3] = __expf(sc[nt][3] - mn1); ps1 += sc[nt][3];
            }
            #pragma unroll
            for (int off = 1; off <= 2; off <<= 1) {
                ps0 += __shfl_xor_sync(0xFFFFFFFFu, ps0, off);
                ps1 += __shfl_xor_sync(0xFFFFFFFFu, ps1, off);
            }
            ls0 = ls0 * cc0 + ps0;
            ls1 = ls1 * cc1 + ps1;
            #pragma unroll
            for (int nt = 0; nt < 8; nt++) {
                o[nt][0] *= cc0; o[nt][1] *= cc0;
                o[nt][2] *= cc1; o[nt][3] *= cc1;
            }

            __syncwarp();
            #pragma unroll
            for (int nt = 0; nt < 8; nt++) {
                int c0 = nt * 8 + tig * 2;
                __half2 p0 = __floats2half2_rn(sc[nt][0], sc[nt][1]);
                __half2 p1 = __floats2half2_rn(sc[nt][2], sc[nt][3]);
                *(__half2*)(QP + (m0 + gid    ) * AROW + c0 * 2) = p0;
                *(__half2*)(QP + (m0 + gid + 8) * AROW + c0 * 2) = p1;
            }
            __syncwarp();

            #pragma unroll
            for (int ks = 0; ks < 4; ks++) {
                uint32_t pf[4];
                ldsm_x4(pf[0], pf[1], pf[2], pf[3], p_lm + ks * 32);
                uint32_t v_base = sbV + stg * KV_STAGE + (ks * 16 + (lane & 15)) * AROW
                                + ((lane >> 4) * 16);
                #pragma unroll
                for (int p = 0; p < 4; p++) {
                    uint32_t bf[2][2];
                    ldsm_x4_t(bf[0][0], bf[0][1], bf[1][0], bf[1][1], v_base + p * 32);
                    mma_f16(o[2*p    ], pf, bf[0]);
                    mma_f16(o[2*p + 1], pf, bf[1]);
                }
            }
        }
    }

    float inv0 = 1.0f / ls0, inv1 = 1.0f / ls1;
    int row0 = b * SEQ + q0 + m0 + gid;
    int row1 = row0 + 8;
    #pragma unroll
    for (int nt = 0; nt < 8; nt++) {
        int col = h * HD + nt * 8 + tig * 2;
        *(__half2*)(out + (size_t)row0 * D_MODEL + col) = __floats2half2_rn(o[nt][0] * inv0, o[nt][1] * inv0);
        *(__half2*)(out + (size_t)row1 * D_MODEL + col) = __floats2half2_rn(o[nt][2] * inv1, o[nt][3] * inv1);
    }
}

// ---------------- launch ----------------
extern "C" void kernel_launch(void* const* d_in, const int* in_sizes, int n_in,
                              void* d_out, int out_size)
{
    const float* x          = (const float*)d_in[0];
    const float* ln1_w      = (const float*)d_in[1];
    const float* ln1_b      = (const float*)d_in[2];
    const float* qkv_w      = (const float*)d_in[3];
    const float* qkv_b      = (const float*)d_in[4];
    const float* attn_out_w = (const float*)d_in[5];
    const float* attn_out_b = (const float*)d_in[6];
    const float* ln2_w      = (const float*)d_in[7];
    const float* ln2_b      = (const float*)d_in[8];
    const float* c_fc_w     = (const float*)d_in[9];
    const float* c_fc_b     = (const float*)d_in[10];
    const float* c_proj_w   = (const float*)d_in[11];
    const float* c_proj_b   = (const float*)d_in[12];
    float* out = (float*)d_out;

    float *XN, *H, *HN;
    __half *XNh, *QKVh, *Oh, *HNh, *Gh, *Wqkv, *Wproj, *Wfc, *Wpr2;
    cudaGetSymbolAddress((void**)&XN,   g_XN);
    cudaGetSymbolAddress((void**)&XNh,  g_XNh);
    cudaGetSymbolAddress((void**)&QKVh, g_QKVh);
    cudaGetSymbolAddress((void**)&Oh,   g_Oh);
    cudaGetSymbolAddress((void**)&H,    g_H);
    cudaGetSymbolAddress((void**)&HN,   g_HN);
    cudaGetSymbolAddress((void**)&HNh,  g_HNh);
    cudaGetSymbolAddress((void**)&Gh,   g_Gh);
    cudaGetSymbolAddress((void**)&Wqkv, g_Wqkv);
    cudaGetSymbolAddress((void**)&Wproj,g_Wproj);
    cudaGetSymbolAddress((void**)&Wfc,  g_Wfc);
    cudaGetSymbolAddress((void**)&Wpr2, g_Wpr2);

    cudaFuncSetAttribute(mma_gemm<EPI_BIAS_QKV>,  cudaFuncAttributeMaxDynamicSharedMemorySize, GEMM_SMEM_BYTES);
    cudaFuncSetAttribute(mma_gemm<EPI_BIAS_GELU>, cudaFuncAttributeMaxDynamicSharedMemorySize, GEMM_SMEM_BYTES);
    cudaFuncSetAttribute(mma_gemm<EPI_BIAS_RES>,  cudaFuncAttributeMaxDynamicSharedMemorySize, GEMM_SMEM_BYTES);
    cudaFuncSetAttribute(attn_kernel,             cudaFuncAttributeMaxDynamicSharedMemorySize, ATTN_SMEM);

    cvt_all_kernel<<<12288, 256>>>(qkv_w, attn_out_w, c_fc_w, c_proj_w,
                                   Wqkv, Wproj, Wfc, Wpr2);

    ln_kernel<<<ROWS / 8, 256>>>(x, ln1_w, ln1_b, XN, XNh);

    mma_gemm<EPI_BIAS_QKV><<<dim3(3 * D_MODEL / 128, ROWS / 128), 256, GEMM_SMEM_BYTES>>>(
        XNh, Wqkv, qkv_b, nullptr, QKVh, ROWS, 3 * D_MODEL, D_MODEL);

    attn_kernel<<<dim3(SEQ / 128, BATCH * NHEAD), 256, ATTN_SMEM>>>(QKVh, Oh);

    mma_gemm<EPI_BIAS_RES><<<dim3(D_MODEL / 128, ROWS / 128), 256, GEMM_SMEM_BYTES>>>(
        Oh, Wproj, attn_out_b, XN, H, ROWS, D_MODEL, D_MODEL);

    ln_kernel<<<ROWS / 8, 256>>>(H, ln2_w, ln2_b, HN, HNh);

    mma_gemm<EPI_BIAS_GELU><<<dim3(4 * D_MODEL / 128, ROWS / 128), 256, GEMM_SMEM_BYTES>>>(
        HNh, Wfc, c_fc_b, nullptr, Gh, ROWS, 4 * D_MODEL, D_MODEL);

    mma_gemm<EPI_BIAS_RES><<<dim3(D_MODEL / 128, ROWS / 128), 256, GEMM_SMEM_BYTES>>>(
        Gh, Wpr2, c_proj_b, HN, out, ROWS, D_MODEL, 4 * D_MODEL);
}